// round 1
// baseline (speedup 1.0000x reference)
#include <cuda_runtime.h>
#include <math.h>

#define BATCH 2
#define SEQ 2048
#define DMODEL 2048
#define NHEAD 16
#define HDIM 128
#define MROWS (BATCH * SEQ)          // 4096
#define ATT_SCALE 0.08838834764831845f  // 1/sqrt(128)

// Scratch (device globals: allocation-free per harness rules)
__device__ float g_q[(size_t)MROWS * DMODEL];
__device__ float g_k[(size_t)MROWS * DMODEL];
__device__ float g_v[(size_t)MROWS * DMODEL];
__device__ float g_att[(size_t)MROWS * DMODEL];

// ---------------------------------------------------------------------------
// GEMM: C[M,N] = A[M,K] @ W[N,K]^T + bias[N]
// BM=BN=128, BK=16, 256 threads, 8x8 microtile, double-buffered smem.
// ---------------------------------------------------------------------------
#define GBM 128
#define GBN 128
#define GBK 16

__global__ __launch_bounds__(256, 2)
void gemm_xwt(const float* __restrict__ A, const float* __restrict__ W,
              const float* __restrict__ bias, float* __restrict__ C,
              int M, int N, int K)
{
    __shared__ float As[2][GBK][GBM];
    __shared__ float Ws[2][GBK][GBN];

    const int tid = threadIdx.x;
    const int tx = tid & 15;
    const int ty = tid >> 4;
    const int m0 = blockIdx.y * GBM;
    const int n0 = blockIdx.x * GBN;

    // tile load mapping: 512 float4 slots per operand, 2 per thread
    // slot u0 = tid       -> row r0 = tid>>2,      k4 = tid&3
    // slot u1 = tid+256   -> row r0+64,            k4 same
    const int r0 = tid >> 2;
    const int c0 = tid & 3;

    const float* Abase = A + (size_t)m0 * K;
    const float* Wbase = W + (size_t)n0 * K;

    float acc[8][8];
#pragma unroll
    for (int i = 0; i < 8; i++)
#pragma unroll
        for (int j = 0; j < 8; j++) acc[i][j] = 0.0f;

    float4 a0, a1, w0, w1;

    // prefetch tile 0
    a0 = *(const float4*)(Abase + (size_t)r0 * K + c0 * 4);
    a1 = *(const float4*)(Abase + (size_t)(r0 + 64) * K + c0 * 4);
    w0 = *(const float4*)(Wbase + (size_t)r0 * K + c0 * 4);
    w1 = *(const float4*)(Wbase + (size_t)(r0 + 64) * K + c0 * 4);

    // store tile 0 into buffer 0 (transposed: [k][m])
    {
        As[0][c0 * 4 + 0][r0] = a0.x; As[0][c0 * 4 + 1][r0] = a0.y;
        As[0][c0 * 4 + 2][r0] = a0.z; As[0][c0 * 4 + 3][r0] = a0.w;
        As[0][c0 * 4 + 0][r0 + 64] = a1.x; As[0][c0 * 4 + 1][r0 + 64] = a1.y;
        As[0][c0 * 4 + 2][r0 + 64] = a1.z; As[0][c0 * 4 + 3][r0 + 64] = a1.w;
        Ws[0][c0 * 4 + 0][r0] = w0.x; Ws[0][c0 * 4 + 1][r0] = w0.y;
        Ws[0][c0 * 4 + 2][r0] = w0.z; Ws[0][c0 * 4 + 3][r0] = w0.w;
        Ws[0][c0 * 4 + 0][r0 + 64] = w1.x; Ws[0][c0 * 4 + 1][r0 + 64] = w1.y;
        Ws[0][c0 * 4 + 2][r0 + 64] = w1.z; Ws[0][c0 * 4 + 3][r0 + 64] = w1.w;
    }
    __syncthreads();

    const int nt = K / GBK;
    for (int t = 0; t < nt; ++t) {
        const int buf = t & 1;

        if (t + 1 < nt) {
            const int koff = (t + 1) * GBK;
            a0 = *(const float4*)(Abase + (size_t)r0 * K + koff + c0 * 4);
            a1 = *(const float4*)(Abase + (size_t)(r0 + 64) * K + koff + c0 * 4);
            w0 = *(const float4*)(Wbase + (size_t)r0 * K + koff + c0 * 4);
            w1 = *(const float4*)(Wbase + (size_t)(r0 + 64) * K + koff + c0 * 4);
        }

#pragma unroll
        for (int kk = 0; kk < GBK; ++kk) {
            float af[8], wf[8];
#pragma unroll
            for (int i = 0; i < 8; i++) af[i] = As[buf][kk][ty * 8 + i];
#pragma unroll
            for (int j = 0; j < 8; j++) wf[j] = Ws[buf][kk][tx + 16 * j];
#pragma unroll
            for (int i = 0; i < 8; i++)
#pragma unroll
                for (int j = 0; j < 8; j++)
                    acc[i][j] = fmaf(af[i], wf[j], acc[i][j]);
        }

        if (t + 1 < nt) {
            const int nb = buf ^ 1;
            As[nb][c0 * 4 + 0][r0] = a0.x; As[nb][c0 * 4 + 1][r0] = a0.y;
            As[nb][c0 * 4 + 2][r0] = a0.z; As[nb][c0 * 4 + 3][r0] = a0.w;
            As[nb][c0 * 4 + 0][r0 + 64] = a1.x; As[nb][c0 * 4 + 1][r0 + 64] = a1.y;
            As[nb][c0 * 4 + 2][r0 + 64] = a1.z; As[nb][c0 * 4 + 3][r0 + 64] = a1.w;
            Ws[nb][c0 * 4 + 0][r0] = w0.x; Ws[nb][c0 * 4 + 1][r0] = w0.y;
            Ws[nb][c0 * 4 + 2][r0] = w0.z; Ws[nb][c0 * 4 + 3][r0] = w0.w;
            Ws[nb][c0 * 4 + 0][r0 + 64] = w1.x; Ws[nb][c0 * 4 + 1][r0 + 64] = w1.y;
            Ws[nb][c0 * 4 + 2][r0 + 64] = w1.z; Ws[nb][c0 * 4 + 3][r0 + 64] = w1.w;
        }
        __syncthreads();
    }

    // epilogue: add bias, store (coalesced across tx)
#pragma unroll
    for (int i = 0; i < 8; i++) {
        const int row = m0 + ty * 8 + i;
#pragma unroll
        for (int j = 0; j < 8; j++) {
            const int col = n0 + tx + 16 * j;
            C[(size_t)row * N + col] = acc[i][j] + __ldg(&bias[col]);
        }
    }
}

// ---------------------------------------------------------------------------
// Causal flash attention (fp32). One CTA per (b, h, 128-row q tile).
// smem: Qs[128][132], Ks[128][132] (reused for P), Vs[128][132]
// ---------------------------------------------------------------------------
#define FBQ 128
#define FBK 128
#define FRS 132

extern __shared__ float fsm[];

__global__ __launch_bounds__(256, 1)
void flash_attn(const float* __restrict__ Q, const float* __restrict__ K,
                const float* __restrict__ V, float* __restrict__ O)
{
    float* Qs = fsm;
    float* Ks = fsm + 128 * FRS;   // reused as P after scores
    float* Vs = fsm + 2 * 128 * FRS;

    const int qt = blockIdx.x;
    const int h = blockIdx.y;
    const int b = blockIdx.z;
    const int q0 = qt * FBQ;
    const size_t headoff = (size_t)b * SEQ * DMODEL + (size_t)h * HDIM;
    const float* Qb = Q + headoff;
    const float* Kb = K + headoff;
    const float* Vb = V + headoff;

    const int tid = threadIdx.x;
    const int tx = tid & 15;
    const int ty = tid >> 4;

    // load Q tile (128 rows x 128 cols = 4096 float4; 16 per thread)
#pragma unroll
    for (int u = 0; u < 16; ++u) {
        const int slot = tid + u * 256;
        const int r = slot >> 5;
        const int d4 = slot & 31;
        float4 v = *(const float4*)(Qb + (size_t)(q0 + r) * DMODEL + d4 * 4);
        *(float4*)(Qs + r * FRS + d4 * 4) = v;
    }

    float m_i[8], l_i[8], acc[8][8];
#pragma unroll
    for (int i = 0; i < 8; i++) {
        m_i[i] = -INFINITY;
        l_i[i] = 0.0f;
#pragma unroll
        for (int j = 0; j < 8; j++) acc[i][j] = 0.0f;
    }

    for (int kt = 0; kt <= qt; ++kt) {
        const int k0 = kt * FBK;
        __syncthreads();  // prior PV reads of Ks/Vs complete (also covers Q load at kt=0)

#pragma unroll
        for (int u = 0; u < 16; ++u) {
            const int slot = tid + u * 256;
            const int r = slot >> 5;
            const int d4 = slot & 31;
            float4 kv = *(const float4*)(Kb + (size_t)(k0 + r) * DMODEL + d4 * 4);
            float4 vv = *(const float4*)(Vb + (size_t)(k0 + r) * DMODEL + d4 * 4);
            *(float4*)(Ks + r * FRS + d4 * 4) = kv;
            *(float4*)(Vs + r * FRS + d4 * 4) = vv;
        }
        __syncthreads();

        // scores: s[i][j] = Q[ty*8+i] . K[tx+16*j]
        float s[8][8];
#pragma unroll
        for (int i = 0; i < 8; i++)
#pragma unroll
            for (int j = 0; j < 8; j++) s[i][j] = 0.0f;

#pragma unroll 2
        for (int d = 0; d < HDIM; ++d) {
            float qf[8], kf[8];
#pragma unroll
            for (int i = 0; i < 8; i++) qf[i] = Qs[(ty * 8 + i) * FRS + d];
#pragma unroll
            for (int j = 0; j < 8; j++) kf[j] = Ks[(tx + 16 * j) * FRS + d];
#pragma unroll
            for (int i = 0; i < 8; i++)
#pragma unroll
                for (int j = 0; j < 8; j++)
                    s[i][j] = fmaf(qf[i], kf[j], s[i][j]);
        }

        // scale + causal mask (only the diagonal tile has masked entries)
        const bool diag = (kt == qt);
#pragma unroll
        for (int i = 0; i < 8; i++)
#pragma unroll
            for (int j = 0; j < 8; j++) {
                float v = s[i][j] * ATT_SCALE;
                if (diag && (tx + 16 * j) > (ty * 8 + i)) v = -1e30f;
                s[i][j] = v;
            }

        // online softmax update
#pragma unroll
        for (int i = 0; i < 8; i++) {
            float rm = s[i][0];
#pragma unroll
            for (int j = 1; j < 8; j++) rm = fmaxf(rm, s[i][j]);
#pragma unroll
            for (int off = 8; off > 0; off >>= 1)
                rm = fmaxf(rm, __shfl_xor_sync(0xffffffffu, rm, off));
            const float mnew = fmaxf(m_i[i], rm);
            const float corr = __expf(m_i[i] - mnew);
            float sum = 0.0f;
#pragma unroll
            for (int j = 0; j < 8; j++) {
                s[i][j] = __expf(s[i][j] - mnew);
                sum += s[i][j];
            }
#pragma unroll
            for (int off = 8; off > 0; off >>= 1)
                sum += __shfl_xor_sync(0xffffffffu, sum, off);
            l_i[i] = l_i[i] * corr + sum;
            m_i[i] = mnew;
#pragma unroll
            for (int j = 0; j < 8; j++) acc[i][j] *= corr;
        }

        // write P into the K buffer
        __syncthreads();
#pragma unroll
        for (int i = 0; i < 8; i++)
#pragma unroll
            for (int j = 0; j < 8; j++)
                Ks[(ty * 8 + i) * FRS + tx + 16 * j] = s[i][j];
        __syncthreads();

        // acc += P @ V
#pragma unroll 2
        for (int kk = 0; kk < FBK; ++kk) {
            float pf[8], vf[8];
#pragma unroll
            for (int i = 0; i < 8; i++) pf[i] = Ks[(ty * 8 + i) * FRS + kk];
#pragma unroll
            for (int j = 0; j < 8; j++) vf[j] = Vs[kk * FRS + tx + 16 * j];
#pragma unroll
            for (int i = 0; i < 8; i++)
#pragma unroll
                for (int j = 0; j < 8; j++)
                    acc[i][j] = fmaf(pf[i], vf[j], acc[i][j]);
        }
    }

    // normalize + store
#pragma unroll
    for (int i = 0; i < 8; i++) {
        const float inv = 1.0f / l_i[i];
        const size_t rowbase = headoff + (size_t)(q0 + ty * 8 + i) * DMODEL;
#pragma unroll
        for (int j = 0; j < 8; j++)
            O[rowbase + tx + 16 * j] = acc[i][j] * inv;
    }
}

// ---------------------------------------------------------------------------
extern "C" void kernel_launch(void* const* d_in, const int* in_sizes, int n_in,
                              void* d_out, int out_size)
{
    const float* query = (const float*)d_in[0];
    const float* key_i = (const float*)d_in[1];
    const float* value = (const float*)d_in[2];
    const float* Wq = (const float*)d_in[3];
    const float* bq = (const float*)d_in[4];
    const float* Wk = (const float*)d_in[5];
    const float* bk = (const float*)d_in[6];
    const float* Wv = (const float*)d_in[7];
    const float* bv = (const float*)d_in[8];
    const float* Wo = (const float*)d_in[9];
    const float* bo = (const float*)d_in[10];
    float* out = (float*)d_out;

    float *pq, *pk, *pv, *pa;
    cudaGetSymbolAddress((void**)&pq, g_q);
    cudaGetSymbolAddress((void**)&pk, g_k);
    cudaGetSymbolAddress((void**)&pv, g_v);
    cudaGetSymbolAddress((void**)&pa, g_att);

    const dim3 ggrid(DMODEL / GBN, MROWS / GBM);

    gemm_xwt<<<ggrid, 256>>>(query, Wq, bq, pq, MROWS, DMODEL, DMODEL);
    gemm_xwt<<<ggrid, 256>>>(key_i, Wk, bk, pk, MROWS, DMODEL, DMODEL);
    gemm_xwt<<<ggrid, 256>>>(value, Wv, bv, pv, MROWS, DMODEL, DMODEL);

    const size_t fsmem = (size_t)3 * 128 * FRS * sizeof(float);  // 202,752 B
    cudaFuncSetAttribute(flash_attn, cudaFuncAttributeMaxDynamicSharedMemorySize,
                         (int)fsmem);
    const dim3 agrid(SEQ / FBQ, NHEAD, BATCH);
    flash_attn<<<agrid, 256, fsmem>>>(pq, pk, pv, pa);

    gemm_xwt<<<ggrid, 256>>>(pa, Wo, bo, out, MROWS, DMODEL, DMODEL);
}

// round 3
// speedup vs baseline: 2.1625x; 2.1625x over previous
#include <cuda_runtime.h>
#include <math.h>
#include <stdint.h>

#define BATCH 2
#define SEQ 2048
#define DMODEL 2048
#define NHEAD 16
#define HDIM 128
#define MROWS (BATCH * SEQ)          // 4096
#define ATT_SCALE 0.08838834764831845f  // 1/sqrt(128)

// Scratch (device globals: allocation-free per harness rules)
__device__ float g_q[(size_t)MROWS * DMODEL];
__device__ float g_k[(size_t)MROWS * DMODEL];
__device__ float g_v[(size_t)MROWS * DMODEL];
__device__ float g_att[(size_t)MROWS * DMODEL];
// tf32-rounded operands
__device__ float r_q[(size_t)MROWS * DMODEL];
__device__ float r_k[(size_t)MROWS * DMODEL];
__device__ float r_v[(size_t)MROWS * DMODEL];
__device__ float r_wq[(size_t)DMODEL * DMODEL];
__device__ float r_wk[(size_t)DMODEL * DMODEL];
__device__ float r_wv[(size_t)DMODEL * DMODEL];
__device__ float r_wo[(size_t)DMODEL * DMODEL];

// ===========================================================================
// tf32 RNA rounding pass (elementwise, float4-vectorized)
// ===========================================================================
__device__ __forceinline__ float rna_tf32(float x) {
    uint32_t u;
    asm("cvt.rna.tf32.f32 %0, %1;" : "=r"(u) : "f"(x));
    return __uint_as_float(u);
}

__global__ void round_tf32_k(const float4* __restrict__ in,
                             float4* __restrict__ out, int n4)
{
    int i = blockIdx.x * blockDim.x + threadIdx.x;
    if (i >= n4) return;
    float4 v = in[i];
    v.x = rna_tf32(v.x); v.y = rna_tf32(v.y);
    v.z = rna_tf32(v.z); v.w = rna_tf32(v.w);
    out[i] = v;
}

// ===========================================================================
// tf32 mma.sync GEMM: C[M,2048] = A[M,2048] @ W[2048,2048]^T + bias
// CTA tile 128x256, BK=32, 3-stage cp.async pipeline, 8 warps (64x64 each).
// Inputs A, W must already be tf32-rounded.
// ===========================================================================
#define TBM 128
#define TBN 256
#define TBK 32
#define GK 2048
#define GN 2048
#define APAD 36
#define ASTG (TBM * APAD)            // 4608 floats
#define BSTG (TBN * APAD)            // 9216 floats
#define STG_FLOATS (ASTG + BSTG)     // 13824 floats
#define NSTAGE 3
#define GEMM_SMEM (NSTAGE * STG_FLOATS * 4)  // 165888 B
#define NT (GK / TBK)                // 64

__device__ __forceinline__ void cp16(uint32_t dst, const void* src) {
    asm volatile("cp.async.cg.shared.global [%0], [%1], 16;"
                 :: "r"(dst), "l"(src));
}

__device__ __forceinline__ void mma_tf32(float* d, const uint32_t* a,
                                         const uint32_t* b)
{
    asm volatile(
        "mma.sync.aligned.m16n8k8.row.col.f32.tf32.tf32.f32 "
        "{%0,%1,%2,%3}, {%4,%5,%6,%7}, {%8,%9}, {%0,%1,%2,%3};"
        : "+f"(d[0]), "+f"(d[1]), "+f"(d[2]), "+f"(d[3])
        : "r"(a[0]), "r"(a[1]), "r"(a[2]), "r"(a[3]),
          "r"(b[0]), "r"(b[1]));
}

__device__ __forceinline__ uint32_t smem_u32(const void* p) {
    uint32_t a;
    asm("{ .reg .u64 t; cvta.to.shared.u64 t, %1; cvt.u32.u64 %0, t; }"
        : "=r"(a) : "l"(p));
    return a;
}

__global__ __launch_bounds__(256, 1)
void gemm_tc(const float* __restrict__ A, const float* __restrict__ W,
             const float* __restrict__ bias, float* __restrict__ C)
{
    extern __shared__ float gsm[];

    const int tid = threadIdx.x;
    const int lane = tid & 31;
    const int warp = tid >> 5;
    const int wm = warp & 1;          // 2 m-slots of 64
    const int wn = warp >> 1;         // 4 n-slots of 64
    const int m0 = blockIdx.y * TBM;
    const int n0 = blockIdx.x * TBN;

    const uint32_t sbase = smem_u32(gsm);

    // per-thread cp.async mapping (idx = tid + i*256 -> row idx>>3, chunk idx&7)
    const int cr = tid >> 3;          // base row (A: +32*i has... recomputed below)
    const int cc = tid & 7;           // 16B chunk within 32-float row

    float acc[4][8][4];
#pragma unroll
    for (int i = 0; i < 4; i++)
#pragma unroll
        for (int j = 0; j < 8; j++)
#pragma unroll
            for (int r = 0; r < 4; r++) acc[i][j][r] = 0.0f;

    auto issue = [&](int t, int buf) {
        const float* Ab = A + (size_t)m0 * GK + t * TBK;
        const float* Wb = W + (size_t)n0 * GK + t * TBK;
        const uint32_t sa = sbase + (uint32_t)buf * STG_FLOATS * 4u;
        const uint32_t sb = sa + ASTG * 4u;
#pragma unroll
        for (int i = 0; i < 4; i++) {
            const int r = cr + i * 32;
            cp16(sa + (uint32_t)(r * APAD + cc * 4) * 4u,
                 Ab + (size_t)r * GK + cc * 4);
        }
#pragma unroll
        for (int i = 0; i < 8; i++) {
            const int r = cr + i * 32;
            cp16(sb + (uint32_t)(r * APAD + cc * 4) * 4u,
                 Wb + (size_t)r * GK + cc * 4);
        }
        asm volatile("cp.async.commit_group;");
    };

    issue(0, 0);
    issue(1, 1);

    for (int t = 0; t < NT; ++t) {
        if (t + 1 < NT) {
            asm volatile("cp.async.wait_group 1;");
        } else {
            asm volatile("cp.async.wait_group 0;");
        }
        __syncthreads();
        if (t + 2 < NT) issue(t + 2, (t + 2) % 3);

        const float* As = gsm + (t % 3) * STG_FLOATS;
        const float* Bs = As + ASTG;

#pragma unroll
        for (int ks = 0; ks < 4; ++ks) {
            const int c0 = ks * 8 + (lane & 3);
            uint32_t a[4][4], b[8][2];
#pragma unroll
            for (int ms = 0; ms < 4; ms++) {
                const int r0 = wm * 64 + ms * 16 + (lane >> 2);
                a[ms][0] = __float_as_uint(As[r0 * APAD + c0]);
                a[ms][1] = __float_as_uint(As[(r0 + 8) * APAD + c0]);
                a[ms][2] = __float_as_uint(As[r0 * APAD + c0 + 4]);
                a[ms][3] = __float_as_uint(As[(r0 + 8) * APAD + c0 + 4]);
            }
#pragma unroll
            for (int ns = 0; ns < 8; ns++) {
                const int nr = wn * 64 + ns * 8 + (lane >> 2);
                b[ns][0] = __float_as_uint(Bs[nr * APAD + c0]);
                b[ns][1] = __float_as_uint(Bs[nr * APAD + c0 + 4]);
            }
#pragma unroll
            for (int ms = 0; ms < 4; ms++)
#pragma unroll
                for (int ns = 0; ns < 8; ns++)
                    mma_tf32(acc[ms][ns], a[ms], b[ns]);
        }
    }

    // epilogue: bias + direct STG.64
    float2 bv[8];
#pragma unroll
    for (int ns = 0; ns < 8; ns++) {
        const int col = n0 + wn * 64 + ns * 8 + 2 * (lane & 3);
        bv[ns] = *(const float2*)(bias + col);
    }
#pragma unroll
    for (int ms = 0; ms < 4; ms++) {
        const int row0 = m0 + wm * 64 + ms * 16 + (lane >> 2);
#pragma unroll
        for (int ns = 0; ns < 8; ns++) {
            const int col = n0 + wn * 64 + ns * 8 + 2 * (lane & 3);
            float2 v0 = make_float2(acc[ms][ns][0] + bv[ns].x,
                                    acc[ms][ns][1] + bv[ns].y);
            float2 v1 = make_float2(acc[ms][ns][2] + bv[ns].x,
                                    acc[ms][ns][3] + bv[ns].y);
            *(float2*)(C + (size_t)row0 * GN + col) = v0;
            *(float2*)(C + (size_t)(row0 + 8) * GN + col) = v1;
        }
    }
}

// ---------------------------------------------------------------------------
// Causal flash attention (fp32). One CTA per (b, h, 128-row q tile).
// (unchanged known-good kernel; mma.sync conversion is the next round)
// ---------------------------------------------------------------------------
#define FBQ 128
#define FBK 128
#define FRS 132

extern __shared__ float fsm[];

__global__ __launch_bounds__(256, 1)
void flash_attn(const float* __restrict__ Q, const float* __restrict__ K,
                const float* __restrict__ V, float* __restrict__ O)
{
    float* Qs = fsm;
    float* Ks = fsm + 128 * FRS;   // reused as P after scores
    float* Vs = fsm + 2 * 128 * FRS;

    const int qt = blockIdx.x;
    const int h = blockIdx.y;
    const int b = blockIdx.z;
    const int q0 = qt * FBQ;
    const size_t headoff = (size_t)b * SEQ * DMODEL + (size_t)h * HDIM;
    const float* Qb = Q + headoff;
    const float* Kb = K + headoff;
    const float* Vb = V + headoff;

    const int tid = threadIdx.x;
    const int tx = tid & 15;
    const int ty = tid >> 4;

#pragma unroll
    for (int u = 0; u < 16; ++u) {
        const int slot = tid + u * 256;
        const int r = slot >> 5;
        const int d4 = slot & 31;
        float4 v = *(const float4*)(Qb + (size_t)(q0 + r) * DMODEL + d4 * 4);
        *(float4*)(Qs + r * FRS + d4 * 4) = v;
    }

    float m_i[8], l_i[8], acc[8][8];
#pragma unroll
    for (int i = 0; i < 8; i++) {
        m_i[i] = -INFINITY;
        l_i[i] = 0.0f;
#pragma unroll
        for (int j = 0; j < 8; j++) acc[i][j] = 0.0f;
    }

    for (int kt = 0; kt <= qt; ++kt) {
        const int k0 = kt * FBK;
        __syncthreads();

#pragma unroll
        for (int u = 0; u < 16; ++u) {
            const int slot = tid + u * 256;
            const int r = slot >> 5;
            const int d4 = slot & 31;
            float4 kv = *(const float4*)(Kb + (size_t)(k0 + r) * DMODEL + d4 * 4);
            float4 vv = *(const float4*)(Vb + (size_t)(k0 + r) * DMODEL + d4 * 4);
            *(float4*)(Ks + r * FRS + d4 * 4) = kv;
            *(float4*)(Vs + r * FRS + d4 * 4) = vv;
        }
        __syncthreads();

        float s[8][8];
#pragma unroll
        for (int i = 0; i < 8; i++)
#pragma unroll
            for (int j = 0; j < 8; j++) s[i][j] = 0.0f;

#pragma unroll 2
        for (int d = 0; d < HDIM; ++d) {
            float qf[8], kf[8];
#pragma unroll
            for (int i = 0; i < 8; i++) qf[i] = Qs[(ty * 8 + i) * FRS + d];
#pragma unroll
            for (int j = 0; j < 8; j++) kf[j] = Ks[(tx + 16 * j) * FRS + d];
#pragma unroll
            for (int i = 0; i < 8; i++)
#pragma unroll
                for (int j = 0; j < 8; j++)
                    s[i][j] = fmaf(qf[i], kf[j], s[i][j]);
        }

        const bool diag = (kt == qt);
#pragma unroll
        for (int i = 0; i < 8; i++)
#pragma unroll
            for (int j = 0; j < 8; j++) {
                float v = s[i][j] * ATT_SCALE;
                if (diag && (tx + 16 * j) > (ty * 8 + i)) v = -1e30f;
                s[i][j] = v;
            }

#pragma unroll
        for (int i = 0; i < 8; i++) {
            float rm = s[i][0];
#pragma unroll
            for (int j = 1; j < 8; j++) rm = fmaxf(rm, s[i][j]);
#pragma unroll
            for (int off = 8; off > 0; off >>= 1)
                rm = fmaxf(rm, __shfl_xor_sync(0xffffffffu, rm, off));
            const float mnew = fmaxf(m_i[i], rm);
            const float corr = __expf(m_i[i] - mnew);
            float sum = 0.0f;
#pragma unroll
            for (int j = 0; j < 8; j++) {
                s[i][j] = __expf(s[i][j] - mnew);
                sum += s[i][j];
            }
#pragma unroll
            for (int off = 8; off > 0; off >>= 1)
                sum += __shfl_xor_sync(0xffffffffu, sum, off);
            l_i[i] = l_i[i] * corr + sum;
            m_i[i] = mnew;
#pragma unroll
            for (int j = 0; j < 8; j++) acc[i][j] *= corr;
        }

        __syncthreads();
#pragma unroll
        for (int i = 0; i < 8; i++)
#pragma unroll
            for (int j = 0; j < 8; j++)
                Ks[(ty * 8 + i) * FRS + tx + 16 * j] = s[i][j];
        __syncthreads();

#pragma unroll 2
        for (int kk = 0; kk < FBK; ++kk) {
            float pf[8], vf[8];
#pragma unroll
            for (int i = 0; i < 8; i++) pf[i] = Ks[(ty * 8 + i) * FRS + kk];
#pragma unroll
            for (int j = 0; j < 8; j++) vf[j] = Vs[kk * FRS + tx + 16 * j];
#pragma unroll
            for (int i = 0; i < 8; i++)
#pragma unroll
                for (int j = 0; j < 8; j++)
                    acc[i][j] = fmaf(pf[i], vf[j], acc[i][j]);
        }
    }

#pragma unroll
    for (int i = 0; i < 8; i++) {
        const float inv = 1.0f / l_i[i];
        const size_t rowbase = headoff + (size_t)(q0 + ty * 8 + i) * DMODEL;
#pragma unroll
        for (int j = 0; j < 8; j++)
            O[rowbase + tx + 16 * j] = acc[i][j] * inv;
    }
}

// ---------------------------------------------------------------------------
extern "C" void kernel_launch(void* const* d_in, const int* in_sizes, int n_in,
                              void* d_out, int out_size)
{
    const float* query = (const float*)d_in[0];
    const float* key_i = (const float*)d_in[1];
    const float* value = (const float*)d_in[2];
    const float* Wq = (const float*)d_in[3];
    const float* bq = (const float*)d_in[4];
    const float* Wk = (const float*)d_in[5];
    const float* bk = (const float*)d_in[6];
    const float* Wv = (const float*)d_in[7];
    const float* bv = (const float*)d_in[8];
    const float* Wo = (const float*)d_in[9];
    const float* bo = (const float*)d_in[10];
    float* out = (float*)d_out;

    float *pq, *pk, *pv, *pa;
    float *rq, *rk, *rv, *rwq, *rwk, *rwv, *rwo;
    cudaGetSymbolAddress((void**)&pq, g_q);
    cudaGetSymbolAddress((void**)&pk, g_k);
    cudaGetSymbolAddress((void**)&pv, g_v);
    cudaGetSymbolAddress((void**)&pa, g_att);
    cudaGetSymbolAddress((void**)&rq, r_q);
    cudaGetSymbolAddress((void**)&rk, r_k);
    cudaGetSymbolAddress((void**)&rv, r_v);
    cudaGetSymbolAddress((void**)&rwq, r_wq);
    cudaGetSymbolAddress((void**)&rwk, r_wk);
    cudaGetSymbolAddress((void**)&rwv, r_wv);
    cudaGetSymbolAddress((void**)&rwo, r_wo);

    const int act4 = (MROWS * DMODEL) / 4;    // 2,097,152 float4
    const int w4 = (DMODEL * DMODEL) / 4;     // 1,048,576 float4
    round_tf32_k<<<(act4 + 255) / 256, 256>>>((const float4*)query, (float4*)rq, act4);
    round_tf32_k<<<(act4 + 255) / 256, 256>>>((const float4*)key_i, (float4*)rk, act4);
    round_tf32_k<<<(act4 + 255) / 256, 256>>>((const float4*)value, (float4*)rv, act4);
    round_tf32_k<<<(w4 + 255) / 256, 256>>>((const float4*)Wq, (float4*)rwq, w4);
    round_tf32_k<<<(w4 + 255) / 256, 256>>>((const float4*)Wk, (float4*)rwk, w4);
    round_tf32_k<<<(w4 + 255) / 256, 256>>>((const float4*)Wv, (float4*)rwv, w4);
    round_tf32_k<<<(w4 + 255) / 256, 256>>>((const float4*)Wo, (float4*)rwo, w4);

    cudaFuncSetAttribute(gemm_tc, cudaFuncAttributeMaxDynamicSharedMemorySize,
                         GEMM_SMEM);
    const dim3 ggrid(GN / TBN, MROWS / TBM);  // (8, 32)

    gemm_tc<<<ggrid, 256, GEMM_SMEM>>>(rq, rwq, bq, pq);
    gemm_tc<<<ggrid, 256, GEMM_SMEM>>>(rk, rwk, bk, pk);
    gemm_tc<<<ggrid, 256, GEMM_SMEM>>>(rv, rwv, bv, pv);

    const size_t fsmem = (size_t)3 * 128 * FRS * sizeof(float);  // 202,752 B
    cudaFuncSetAttribute(flash_attn, cudaFuncAttributeMaxDynamicSharedMemorySize,
                         (int)fsmem);
    const dim3 agrid(SEQ / FBQ, NHEAD, BATCH);
    flash_attn<<<agrid, 256, fsmem>>>(pq, pk, pv, pa);

    // round attention output in place (idempotent), then output projection
    round_tf32_k<<<(act4 + 255) / 256, 256>>>((const float4*)pa, (float4*)pa, act4);
    gemm_tc<<<ggrid, 256, GEMM_SMEM>>>(pa, rwo, bo, out);
}

// round 4
// speedup vs baseline: 3.6919x; 1.7073x over previous
#include <cuda_runtime.h>
#include <math.h>
#include <stdint.h>

#define BATCH 2
#define SEQ 2048
#define DMODEL 2048
#define NHEAD 16
#define HDIM 128
#define MROWS (BATCH * SEQ)          // 4096
#define ATT_SCALE 0.08838834764831845f  // 1/sqrt(128)

// Scratch (device globals: allocation-free per harness rules)
__device__ float g_q[(size_t)MROWS * DMODEL];
__device__ float g_k[(size_t)MROWS * DMODEL];
__device__ float g_v[(size_t)MROWS * DMODEL];
__device__ float g_att[(size_t)MROWS * DMODEL];
// tf32-rounded operands
__device__ float r_q[(size_t)MROWS * DMODEL];
__device__ float r_k[(size_t)MROWS * DMODEL];
__device__ float r_v[(size_t)MROWS * DMODEL];
__device__ float r_wq[(size_t)DMODEL * DMODEL];
__device__ float r_wk[(size_t)DMODEL * DMODEL];
__device__ float r_wv[(size_t)DMODEL * DMODEL];
__device__ float r_wo[(size_t)DMODEL * DMODEL];

// ===========================================================================
// helpers
// ===========================================================================
__device__ __forceinline__ float rna_tf32(float x) {
    uint32_t u;
    asm("cvt.rna.tf32.f32 %0, %1;" : "=r"(u) : "f"(x));
    return __uint_as_float(u);
}

__global__ void round_tf32_k(const float4* __restrict__ in,
                             float4* __restrict__ out, int n4)
{
    int i = blockIdx.x * blockDim.x + threadIdx.x;
    if (i >= n4) return;
    float4 v = in[i];
    v.x = rna_tf32(v.x); v.y = rna_tf32(v.y);
    v.z = rna_tf32(v.z); v.w = rna_tf32(v.w);
    out[i] = v;
}

__device__ __forceinline__ void cp16(uint32_t dst, const void* src) {
    asm volatile("cp.async.cg.shared.global [%0], [%1], 16;"
                 :: "r"(dst), "l"(src));
}

__device__ __forceinline__ void mma_tf32(float* d, const uint32_t* a,
                                         const uint32_t* b)
{
    asm volatile(
        "mma.sync.aligned.m16n8k8.row.col.f32.tf32.tf32.f32 "
        "{%0,%1,%2,%3}, {%4,%5,%6,%7}, {%8,%9}, {%0,%1,%2,%3};"
        : "+f"(d[0]), "+f"(d[1]), "+f"(d[2]), "+f"(d[3])
        : "r"(a[0]), "r"(a[1]), "r"(a[2]), "r"(a[3]),
          "r"(b[0]), "r"(b[1]));
}

__device__ __forceinline__ uint32_t smem_u32(const void* p) {
    uint32_t a;
    asm("{ .reg .u64 t; cvta.to.shared.u64 t, %1; cvt.u32.u64 %0, t; }"
        : "=r"(a) : "l"(p));
    return a;
}

// ===========================================================================
// tf32 mma.sync GEMM: C[M,2048] = A[M,2048] @ W[2048,2048]^T + bias
// CTA tile 128x256, BK=32, 3-stage cp.async pipeline, 8 warps (64x64 each).
// round_out: RNA-round (after *scale) the output to tf32 for downstream MMAs.
// ===========================================================================
#define TBM 128
#define TBN 256
#define TBK 32
#define GK 2048
#define GN 2048
#define APAD 36
#define ASTG (TBM * APAD)            // 4608 floats
#define BSTG (TBN * APAD)            // 9216 floats
#define STG_FLOATS (ASTG + BSTG)     // 13824 floats
#define NSTAGE 3
#define GEMM_SMEM (NSTAGE * STG_FLOATS * 4)  // 165888 B
#define NT (GK / TBK)                // 64

__global__ __launch_bounds__(256, 1)
void gemm_tc(const float* __restrict__ A, const float* __restrict__ W,
             const float* __restrict__ bias, float* __restrict__ C,
             float scale, int round_out)
{
    extern __shared__ float gsm[];

    const int tid = threadIdx.x;
    const int lane = tid & 31;
    const int warp = tid >> 5;
    const int wm = warp & 1;
    const int wn = warp >> 1;
    const int m0 = blockIdx.y * TBM;
    const int n0 = blockIdx.x * TBN;

    const uint32_t sbase = smem_u32(gsm);
    const int cr = tid >> 3;
    const int cc = tid & 7;

    float acc[4][8][4];
#pragma unroll
    for (int i = 0; i < 4; i++)
#pragma unroll
        for (int j = 0; j < 8; j++)
#pragma unroll
            for (int r = 0; r < 4; r++) acc[i][j][r] = 0.0f;

    auto issue = [&](int t, int buf) {
        const float* Ab = A + (size_t)m0 * GK + t * TBK;
        const float* Wb = W + (size_t)n0 * GK + t * TBK;
        const uint32_t sa = sbase + (uint32_t)buf * STG_FLOATS * 4u;
        const uint32_t sb = sa + ASTG * 4u;
#pragma unroll
        for (int i = 0; i < 4; i++) {
            const int r = cr + i * 32;
            cp16(sa + (uint32_t)(r * APAD + cc * 4) * 4u,
                 Ab + (size_t)r * GK + cc * 4);
        }
#pragma unroll
        for (int i = 0; i < 8; i++) {
            const int r = cr + i * 32;
            cp16(sb + (uint32_t)(r * APAD + cc * 4) * 4u,
                 Wb + (size_t)r * GK + cc * 4);
        }
        asm volatile("cp.async.commit_group;");
    };

    issue(0, 0);
    issue(1, 1);

    for (int t = 0; t < NT; ++t) {
        if (t + 1 < NT) {
            asm volatile("cp.async.wait_group 1;");
        } else {
            asm volatile("cp.async.wait_group 0;");
        }
        __syncthreads();
        if (t + 2 < NT) issue(t + 2, (t + 2) % 3);

        const float* As = gsm + (t % 3) * STG_FLOATS;
        const float* Bs = As + ASTG;

#pragma unroll
        for (int ks = 0; ks < 4; ++ks) {
            const int c0 = ks * 8 + (lane & 3);
            uint32_t a[4][4], b[8][2];
#pragma unroll
            for (int ms = 0; ms < 4; ms++) {
                const int r0 = wm * 64 + ms * 16 + (lane >> 2);
                a[ms][0] = __float_as_uint(As[r0 * APAD + c0]);
                a[ms][1] = __float_as_uint(As[(r0 + 8) * APAD + c0]);
                a[ms][2] = __float_as_uint(As[r0 * APAD + c0 + 4]);
                a[ms][3] = __float_as_uint(As[(r0 + 8) * APAD + c0 + 4]);
            }
#pragma unroll
            for (int ns = 0; ns < 8; ns++) {
                const int nr = wn * 64 + ns * 8 + (lane >> 2);
                b[ns][0] = __float_as_uint(Bs[nr * APAD + c0]);
                b[ns][1] = __float_as_uint(Bs[nr * APAD + c0 + 4]);
            }
#pragma unroll
            for (int ms = 0; ms < 4; ms++)
#pragma unroll
                for (int ns = 0; ns < 8; ns++)
                    mma_tf32(acc[ms][ns], a[ms], b[ns]);
        }
    }

    float2 bv[8];
#pragma unroll
    for (int ns = 0; ns < 8; ns++) {
        const int col = n0 + wn * 64 + ns * 8 + 2 * (lane & 3);
        bv[ns] = *(const float2*)(bias + col);
    }
#pragma unroll
    for (int ms = 0; ms < 4; ms++) {
        const int row0 = m0 + wm * 64 + ms * 16 + (lane >> 2);
#pragma unroll
        for (int ns = 0; ns < 8; ns++) {
            const int col = n0 + wn * 64 + ns * 8 + 2 * (lane & 3);
            float2 v0 = make_float2(acc[ms][ns][0] + bv[ns].x,
                                    acc[ms][ns][1] + bv[ns].y);
            float2 v1 = make_float2(acc[ms][ns][2] + bv[ns].x,
                                    acc[ms][ns][3] + bv[ns].y);
            if (round_out) {
                v0.x = rna_tf32(v0.x * scale); v0.y = rna_tf32(v0.y * scale);
                v1.x = rna_tf32(v1.x * scale); v1.y = rna_tf32(v1.y * scale);
            }
            *(float2*)(C + (size_t)row0 * GN + col) = v0;
            *(float2*)(C + (size_t)(row0 + 8) * GN + col) = v1;
        }
    }
}

// ===========================================================================
// tf32 mma.sync causal flash attention.
// One CTA per (b, h, 128-row q tile); 8 warps, warp owns 16 q rows.
// Q pre-scaled by ATT_SCALE and tf32-rounded in GEMM epilogue; K, V rounded.
// ===========================================================================
#define QPAD 132
#define KPAD 132
#define VPAD 136
#define FLASH_SMEM (128 * (QPAD + KPAD + VPAD) * 4)   // 204800 B

__global__ __launch_bounds__(256, 1)
void flash_tc(const float* __restrict__ Q, const float* __restrict__ K,
              const float* __restrict__ V, float* __restrict__ O)
{
    extern __shared__ float fsm2[];
    float* Qs = fsm2;                          // [128][QPAD]
    float* Ks = fsm2 + 128 * QPAD;             // [128][KPAD], reused as P
    float* Vs = fsm2 + 128 * (QPAD + KPAD);    // [128][VPAD]

    const int qt = (SEQ / 128) - 1 - blockIdx.x;   // heavy tiles first
    const int h = blockIdx.y;
    const int b = blockIdx.z;
    const int q0 = qt * 128;
    const size_t headoff = (size_t)b * SEQ * DMODEL + (size_t)h * HDIM;
    const float* Qb = Q + headoff;
    const float* Kb = K + headoff;
    const float* Vb = V + headoff;

    const int tid = threadIdx.x;
    const int lane = tid & 31;
    const int warp = tid >> 5;
    const int g = lane >> 2;      // 0..7
    const int q4 = lane & 3;      // 0..3

    const uint32_t sQ = smem_u32(Qs);
    const uint32_t sK = smem_u32(Ks);
    const uint32_t sV = smem_u32(Vs);

    // Q tile: 128 rows x 32 16B-chunks
#pragma unroll
    for (int i = 0; i < 16; ++i) {
        const int slot = tid + i * 256;
        const int r = slot >> 5, c = slot & 31;
        cp16(sQ + (uint32_t)(r * QPAD + c * 4) * 4u,
             Qb + (size_t)(q0 + r) * DMODEL + c * 4);
    }
    asm volatile("cp.async.commit_group;");

    float m0 = -INFINITY, m1 = -INFINITY, l0 = 0.0f, l1 = 0.0f;
    float acco[16][4];
#pragma unroll
    for (int j = 0; j < 16; j++)
#pragma unroll
        for (int r = 0; r < 4; r++) acco[j][r] = 0.0f;

    const int ar = warp * 16 + g;   // local q row (first of the pair)

    for (int kt = 0; kt <= qt; ++kt) {
        const int k0 = kt * 128;
        __syncthreads();   // all PV reads of Ks/Vs from prev iter done
#pragma unroll
        for (int i = 0; i < 16; ++i) {
            const int slot = tid + i * 256;
            const int r = slot >> 5, c = slot & 31;
            cp16(sK + (uint32_t)(r * KPAD + c * 4) * 4u,
                 Kb + (size_t)(k0 + r) * DMODEL + c * 4);
            cp16(sV + (uint32_t)(r * VPAD + c * 4) * 4u,
                 Vb + (size_t)(k0 + r) * DMODEL + c * 4);
        }
        asm volatile("cp.async.commit_group;");
        asm volatile("cp.async.wait_group 0;");
        __syncthreads();

        // ---- S = Q @ K^T (scale folded into Q) ----
        float accs[16][4];
#pragma unroll
        for (int j = 0; j < 16; j++)
#pragma unroll
            for (int r = 0; r < 4; r++) accs[j][r] = 0.0f;

        for (int ks = 0; ks < 16; ++ks) {
            const int ac = ks * 8 + q4;
            uint32_t a[4];
            a[0] = __float_as_uint(Qs[ar * QPAD + ac]);
            a[1] = __float_as_uint(Qs[(ar + 8) * QPAD + ac]);
            a[2] = __float_as_uint(Qs[ar * QPAD + ac + 4]);
            a[3] = __float_as_uint(Qs[(ar + 8) * QPAD + ac + 4]);
#pragma unroll
            for (int j = 0; j < 16; ++j) {
                uint32_t bb[2];
                bb[0] = __float_as_uint(Ks[(j * 8 + g) * KPAD + ac]);
                bb[1] = __float_as_uint(Ks[(j * 8 + g) * KPAD + ac + 4]);
                mma_tf32(accs[j], a, bb);
            }
        }

        // ---- causal mask (diagonal tile only) ----
        if (kt == qt) {
#pragma unroll
            for (int j = 0; j < 16; ++j) {
                const int c0 = j * 8 + 2 * q4;
                if (c0 > ar)          accs[j][0] = -1e30f;
                if (c0 + 1 > ar)      accs[j][1] = -1e30f;
                if (c0 > ar + 8)      accs[j][2] = -1e30f;
                if (c0 + 1 > ar + 8)  accs[j][3] = -1e30f;
            }
        }

        // ---- online softmax (2 rows per thread; reduce over 4-lane group) --
        float mx0 = -INFINITY, mx1 = -INFINITY;
#pragma unroll
        for (int j = 0; j < 16; ++j) {
            mx0 = fmaxf(mx0, fmaxf(accs[j][0], accs[j][1]));
            mx1 = fmaxf(mx1, fmaxf(accs[j][2], accs[j][3]));
        }
        mx0 = fmaxf(mx0, __shfl_xor_sync(0xffffffffu, mx0, 1));
        mx0 = fmaxf(mx0, __shfl_xor_sync(0xffffffffu, mx0, 2));
        mx1 = fmaxf(mx1, __shfl_xor_sync(0xffffffffu, mx1, 1));
        mx1 = fmaxf(mx1, __shfl_xor_sync(0xffffffffu, mx1, 2));
        const float mn0 = fmaxf(m0, mx0);
        const float mn1 = fmaxf(m1, mx1);
        const float cr0 = __expf(m0 - mn0);
        const float cr1 = __expf(m1 - mn1);
        float s0 = 0.0f, s1 = 0.0f;
#pragma unroll
        for (int j = 0; j < 16; ++j) {
            accs[j][0] = __expf(accs[j][0] - mn0); s0 += accs[j][0];
            accs[j][1] = __expf(accs[j][1] - mn0); s0 += accs[j][1];
            accs[j][2] = __expf(accs[j][2] - mn1); s1 += accs[j][2];
            accs[j][3] = __expf(accs[j][3] - mn1); s1 += accs[j][3];
        }
        s0 += __shfl_xor_sync(0xffffffffu, s0, 1);
        s0 += __shfl_xor_sync(0xffffffffu, s0, 2);
        s1 += __shfl_xor_sync(0xffffffffu, s1, 1);
        s1 += __shfl_xor_sync(0xffffffffu, s1, 2);
        l0 = l0 * cr0 + s0;  m0 = mn0;
        l1 = l1 * cr1 + s1;  m1 = mn1;
#pragma unroll
        for (int j = 0; j < 16; ++j) {
            acco[j][0] *= cr0; acco[j][1] *= cr0;
            acco[j][2] *= cr1; acco[j][3] *= cr1;
        }

        // ---- spill P into the K buffer (own rows only) ----
        __syncthreads();   // all warps done reading Ks for S
#pragma unroll
        for (int j = 0; j < 16; ++j) {
            float2 p0 = make_float2(rna_tf32(accs[j][0]), rna_tf32(accs[j][1]));
            float2 p1 = make_float2(rna_tf32(accs[j][2]), rna_tf32(accs[j][3]));
            *(float2*)(Ks + ar * KPAD + j * 8 + 2 * q4) = p0;
            *(float2*)(Ks + (ar + 8) * KPAD + j * 8 + 2 * q4) = p1;
        }
        __syncwarp();

        // ---- O += P @ V ----
        for (int ks = 0; ks < 16; ++ks) {
            const int ac = ks * 8 + q4;
            uint32_t a[4];
            a[0] = __float_as_uint(Ks[ar * KPAD + ac]);
            a[1] = __float_as_uint(Ks[(ar + 8) * KPAD + ac]);
            a[2] = __float_as_uint(Ks[ar * KPAD + ac + 4]);
            a[3] = __float_as_uint(Ks[(ar + 8) * KPAD + ac + 4]);
#pragma unroll
            for (int j = 0; j < 16; ++j) {
                uint32_t bb[2];
                bb[0] = __float_as_uint(Vs[ac * VPAD + j * 8 + g]);
                bb[1] = __float_as_uint(Vs[(ac + 4) * VPAD + j * 8 + g]);
                mma_tf32(acco[j], a, bb);
            }
        }
    }

    // ---- normalize + store (tf32-rounded for the Wo GEMM) ----
    const float i0 = 1.0f / l0;
    const float i1 = 1.0f / l1;
#pragma unroll
    for (int j = 0; j < 16; ++j) {
        float2 v0 = make_float2(rna_tf32(acco[j][0] * i0),
                                rna_tf32(acco[j][1] * i0));
        float2 v1 = make_float2(rna_tf32(acco[j][2] * i1),
                                rna_tf32(acco[j][3] * i1));
        *(float2*)(O + headoff + (size_t)(q0 + ar) * DMODEL + j * 8 + 2 * q4) = v0;
        *(float2*)(O + headoff + (size_t)(q0 + ar + 8) * DMODEL + j * 8 + 2 * q4) = v1;
    }
}

// ---------------------------------------------------------------------------
extern "C" void kernel_launch(void* const* d_in, const int* in_sizes, int n_in,
                              void* d_out, int out_size)
{
    const float* query = (const float*)d_in[0];
    const float* key_i = (const float*)d_in[1];
    const float* value = (const float*)d_in[2];
    const float* Wq = (const float*)d_in[3];
    const float* bq = (const float*)d_in[4];
    const float* Wk = (const float*)d_in[5];
    const float* bk = (const float*)d_in[6];
    const float* Wv = (const float*)d_in[7];
    const float* bv = (const float*)d_in[8];
    const float* Wo = (const float*)d_in[9];
    const float* bo = (const float*)d_in[10];
    float* out = (float*)d_out;

    float *pq, *pk, *pv, *pa;
    float *rq, *rk, *rv, *rwq, *rwk, *rwv, *rwo;
    cudaGetSymbolAddress((void**)&pq, g_q);
    cudaGetSymbolAddress((void**)&pk, g_k);
    cudaGetSymbolAddress((void**)&pv, g_v);
    cudaGetSymbolAddress((void**)&pa, g_att);
    cudaGetSymbolAddress((void**)&rq, r_q);
    cudaGetSymbolAddress((void**)&rk, r_k);
    cudaGetSymbolAddress((void**)&rv, r_v);
    cudaGetSymbolAddress((void**)&rwq, r_wq);
    cudaGetSymbolAddress((void**)&rwk, r_wk);
    cudaGetSymbolAddress((void**)&rwv, r_wv);
    cudaGetSymbolAddress((void**)&rwo, r_wo);

    const int act4 = (MROWS * DMODEL) / 4;
    const int w4 = (DMODEL * DMODEL) / 4;
    round_tf32_k<<<(act4 + 255) / 256, 256>>>((const float4*)query, (float4*)rq, act4);
    round_tf32_k<<<(act4 + 255) / 256, 256>>>((const float4*)key_i, (float4*)rk, act4);
    round_tf32_k<<<(act4 + 255) / 256, 256>>>((const float4*)value, (float4*)rv, act4);
    round_tf32_k<<<(w4 + 255) / 256, 256>>>((const float4*)Wq, (float4*)rwq, w4);
    round_tf32_k<<<(w4 + 255) / 256, 256>>>((const float4*)Wk, (float4*)rwk, w4);
    round_tf32_k<<<(w4 + 255) / 256, 256>>>((const float4*)Wv, (float4*)rwv, w4);
    round_tf32_k<<<(w4 + 255) / 256, 256>>>((const float4*)Wo, (float4*)rwo, w4);

    cudaFuncSetAttribute(gemm_tc, cudaFuncAttributeMaxDynamicSharedMemorySize,
                         GEMM_SMEM);
    const dim3 ggrid(GN / TBN, MROWS / TBM);  // (8, 32)

    // q pre-scaled by ATT_SCALE; q/k/v rounded to tf32 for the attention MMAs
    gemm_tc<<<ggrid, 256, GEMM_SMEM>>>(rq, rwq, bq, pq, ATT_SCALE, 1);
    gemm_tc<<<ggrid, 256, GEMM_SMEM>>>(rk, rwk, bk, pk, 1.0f, 1);
    gemm_tc<<<ggrid, 256, GEMM_SMEM>>>(rv, rwv, bv, pv, 1.0f, 1);

    cudaFuncSetAttribute(flash_tc, cudaFuncAttributeMaxDynamicSharedMemorySize,
                         FLASH_SMEM);
    const dim3 agrid(SEQ / 128, NHEAD, BATCH);
    flash_tc<<<agrid, 256, FLASH_SMEM>>>(pq, pk, pv, pa);

    // attention output already tf32-rounded; final projection in fp32 out
    gemm_tc<<<ggrid, 256, GEMM_SMEM>>>(pa, rwo, bo, out, 1.0f, 0);
}

// round 5
// speedup vs baseline: 6.9929x; 1.8941x over previous
#include <cuda_runtime.h>
#include <cuda_fp16.h>
#include <math.h>
#include <stdint.h>

#define BATCH 2
#define SEQ 2048
#define DMODEL 2048
#define NHEAD 16
#define HDIM 128
#define MROWS (BATCH * SEQ)          // 4096
#define ATT_SCALE 0.08838834764831845f  // 1/sqrt(128)

// Scratch (device globals: allocation-free per harness rules)
__device__ __half hx_q[(size_t)MROWS * DMODEL];   // fp16 inputs
__device__ __half hx_k[(size_t)MROWS * DMODEL];
__device__ __half hx_v[(size_t)MROWS * DMODEL];
__device__ __half hw_q[(size_t)DMODEL * DMODEL];  // fp16 weights
__device__ __half hw_k[(size_t)DMODEL * DMODEL];
__device__ __half hw_v[(size_t)DMODEL * DMODEL];
__device__ __half hw_o[(size_t)DMODEL * DMODEL];
__device__ __half h_q[(size_t)MROWS * DMODEL];    // projected q (pre-scaled)
__device__ __half h_k[(size_t)MROWS * DMODEL];
__device__ __half h_v[(size_t)MROWS * DMODEL];
__device__ __half h_a[(size_t)MROWS * DMODEL];    // attention output

// ===========================================================================
// helpers
// ===========================================================================
__device__ __forceinline__ uint32_t smem_u32(const void* p) {
    uint32_t a;
    asm("{ .reg .u64 t; cvta.to.shared.u64 t, %1; cvt.u32.u64 %0, t; }"
        : "=r"(a) : "l"(p));
    return a;
}

__device__ __forceinline__ void cp16(uint32_t dst, const void* src) {
    asm volatile("cp.async.cg.shared.global [%0], [%1], 16;"
                 :: "r"(dst), "l"(src));
}

__device__ __forceinline__ void mma_f16(float* d, const uint32_t* a,
                                        const uint32_t* b)
{
    asm volatile(
        "mma.sync.aligned.m16n8k16.row.col.f32.f16.f16.f32 "
        "{%0,%1,%2,%3}, {%4,%5,%6,%7}, {%8,%9}, {%0,%1,%2,%3};"
        : "+f"(d[0]), "+f"(d[1]), "+f"(d[2]), "+f"(d[3])
        : "r"(a[0]), "r"(a[1]), "r"(a[2]), "r"(a[3]),
          "r"(b[0]), "r"(b[1]));
}

__device__ __forceinline__ void ldsm4(uint32_t* r, uint32_t a) {
    asm volatile("ldmatrix.sync.aligned.m8n8.x4.shared.b16 {%0,%1,%2,%3}, [%4];"
                 : "=r"(r[0]), "=r"(r[1]), "=r"(r[2]), "=r"(r[3]) : "r"(a));
}
__device__ __forceinline__ void ldsm2(uint32_t* r, uint32_t a) {
    asm volatile("ldmatrix.sync.aligned.m8n8.x2.shared.b16 {%0,%1}, [%2];"
                 : "=r"(r[0]), "=r"(r[1]) : "r"(a));
}
__device__ __forceinline__ void ldsm2t(uint32_t* r, uint32_t a) {
    asm volatile("ldmatrix.sync.aligned.m8n8.x2.trans.shared.b16 {%0,%1}, [%2];"
                 : "=r"(r[0]), "=r"(r[1]) : "r"(a));
}

// fp32 -> fp16 conversion pass (float4 in, 8B out)
__global__ void f32_to_f16_k(const float4* __restrict__ in,
                             uint2* __restrict__ out, int n4)
{
    int i = blockIdx.x * blockDim.x + threadIdx.x;
    if (i >= n4) return;
    float4 v = in[i];
    union { __half2 h[2]; uint2 u; } p;
    p.h[0] = __floats2half2_rn(v.x, v.y);
    p.h[1] = __floats2half2_rn(v.z, v.w);
    out[i] = p.u;
}

// ===========================================================================
// fp16 mma.sync GEMM: C[M,2048] = A[M,2048] @ W[2048,2048]^T + bias
// CTA tile 128x256, BK=64 halves, 3-stage cp.async, 8 warps (64x64 each).
// half_out: multiply by scale and store fp16 (for downstream MMAs),
// else store fp32.
// ===========================================================================
#define TBM 128
#define TBN 256
#define GK 2048
#define GN 2048
#define GBKH 64
#define AP 72                         // smem pitch (halves): 144B = 4 banks mod 32
#define ASTGH (TBM * AP)              // 9216 halves
#define BSTGH (TBN * AP)              // 18432 halves
#define STGH (ASTGH + BSTGH)          // 27648 halves
#define GEMM_SMEM (3 * STGH * 2)      // 165888 B
#define NT (GK / GBKH)                // 32

__global__ __launch_bounds__(256, 1)
void gemm_tc(const __half* __restrict__ A, const __half* __restrict__ W,
             const float* __restrict__ bias, void* __restrict__ Cout,
             float scale, int half_out)
{
    extern __shared__ __half gsmh[];

    const int tid = threadIdx.x;
    const int lane = tid & 31;
    const int warp = tid >> 5;
    const int wm = warp & 1;
    const int wn = warp >> 1;
    const int m0 = blockIdx.y * TBM;
    const int n0 = blockIdx.x * TBN;

    const uint32_t sbase = smem_u32(gsmh);
    const int cr = tid >> 3;     // 0..31
    const int cc = tid & 7;      // 8-half chunk

    float acc[4][8][4];
#pragma unroll
    for (int i = 0; i < 4; i++)
#pragma unroll
        for (int j = 0; j < 8; j++)
#pragma unroll
            for (int r = 0; r < 4; r++) acc[i][j][r] = 0.0f;

    auto issue = [&](int t, int buf) {
        const __half* Ab = A + (size_t)m0 * GK + t * GBKH;
        const __half* Wb = W + (size_t)n0 * GK + t * GBKH;
        const uint32_t sa = sbase + (uint32_t)buf * STGH * 2u;
        const uint32_t sb = sa + ASTGH * 2u;
#pragma unroll
        for (int i = 0; i < 4; i++) {
            const int r = cr + i * 32;
            cp16(sa + (uint32_t)(r * AP + cc * 8) * 2u,
                 Ab + (size_t)r * GK + cc * 8);
        }
#pragma unroll
        for (int i = 0; i < 8; i++) {
            const int r = cr + i * 32;
            cp16(sb + (uint32_t)(r * AP + cc * 8) * 2u,
                 Wb + (size_t)r * GK + cc * 8);
        }
        asm volatile("cp.async.commit_group;");
    };

    issue(0, 0);
    issue(1, 1);

    // ldmatrix per-lane base offsets (bytes)
    const uint32_t a_lane_off =
        (uint32_t)((wm * 64 + (lane & 15)) * AP + ((lane >> 4) * 8)) * 2u;
    const uint32_t b_lane_off =
        (uint32_t)((wn * 64 + (lane & 7)) * AP + (((lane >> 3) & 1) * 8)) * 2u;

    for (int t = 0; t < NT; ++t) {
        if (t + 1 < NT) {
            asm volatile("cp.async.wait_group 1;");
        } else {
            asm volatile("cp.async.wait_group 0;");
        }
        __syncthreads();
        if (t + 2 < NT) issue(t + 2, (t + 2) % 3);

        const uint32_t sa = sbase + (uint32_t)(t % 3) * STGH * 2u;
        const uint32_t sb = sa + ASTGH * 2u;
        const uint32_t aaddr = sa + a_lane_off;
        const uint32_t baddr = sb + b_lane_off;

#pragma unroll
        for (int ks = 0; ks < 4; ++ks) {
            uint32_t a[4][4], b[8][2];
#pragma unroll
            for (int ms = 0; ms < 4; ms++)
                ldsm4(a[ms], aaddr + (uint32_t)(ms * 16 * AP + ks * 16) * 2u);
#pragma unroll
            for (int ns = 0; ns < 8; ns++)
                ldsm2(b[ns], baddr + (uint32_t)(ns * 8 * AP + ks * 16) * 2u);
#pragma unroll
            for (int ms = 0; ms < 4; ms++)
#pragma unroll
                for (int ns = 0; ns < 8; ns++)
                    mma_f16(acc[ms][ns], a[ms], b[ns]);
        }
    }

    float2 bv[8];
#pragma unroll
    for (int ns = 0; ns < 8; ns++) {
        const int col = n0 + wn * 64 + ns * 8 + 2 * (lane & 3);
        bv[ns] = *(const float2*)(bias + col);
    }

    if (half_out) {
        __half* C = (__half*)Cout;
#pragma unroll
        for (int ms = 0; ms < 4; ms++) {
            const int row0 = m0 + wm * 64 + ms * 16 + (lane >> 2);
#pragma unroll
            for (int ns = 0; ns < 8; ns++) {
                const int col = n0 + wn * 64 + ns * 8 + 2 * (lane & 3);
                __half2 v0 = __floats2half2_rn((acc[ms][ns][0] + bv[ns].x) * scale,
                                               (acc[ms][ns][1] + bv[ns].y) * scale);
                __half2 v1 = __floats2half2_rn((acc[ms][ns][2] + bv[ns].x) * scale,
                                               (acc[ms][ns][3] + bv[ns].y) * scale);
                *(__half2*)(C + (size_t)row0 * GN + col) = v0;
                *(__half2*)(C + (size_t)(row0 + 8) * GN + col) = v1;
            }
        }
    } else {
        float* C = (float*)Cout;
#pragma unroll
        for (int ms = 0; ms < 4; ms++) {
            const int row0 = m0 + wm * 64 + ms * 16 + (lane >> 2);
#pragma unroll
            for (int ns = 0; ns < 8; ns++) {
                const int col = n0 + wn * 64 + ns * 8 + 2 * (lane & 3);
                float2 v0 = make_float2(acc[ms][ns][0] + bv[ns].x,
                                        acc[ms][ns][1] + bv[ns].y);
                float2 v1 = make_float2(acc[ms][ns][2] + bv[ns].x,
                                        acc[ms][ns][3] + bv[ns].y);
                *(float2*)(C + (size_t)row0 * GN + col) = v0;
                *(float2*)(C + (size_t)(row0 + 8) * GN + col) = v1;
            }
        }
    }
}

// ===========================================================================
// fp16 mma.sync causal flash attention, double-buffered K/V.
// One CTA per (b, h, 128-row q tile); 8 warps, warp owns 16 q rows.
// Q pre-scaled by ATT_SCALE. Tiles padded to 136 halves (272B = 4 banks mod 32
// per row -> conflict-free ldmatrix).
// ===========================================================================
#define FP 136
#define TILE_H (128 * FP)                       // halves per tile buffer
#define FLASH_SMEM (TILE_H * 2 * 5)             // Q + 2*K + 2*V = 174080 B

__global__ __launch_bounds__(256, 1)
void flash_tc(const __half* __restrict__ Q, const __half* __restrict__ K,
              const __half* __restrict__ V, __half* __restrict__ O)
{
    extern __shared__ __half fsmh[];

    const int qt = (SEQ / 128) - 1 - blockIdx.x;   // heavy tiles first
    const int h = blockIdx.y;
    const int b = blockIdx.z;
    const int q0 = qt * 128;
    const size_t headoff = (size_t)b * SEQ * DMODEL + (size_t)h * HDIM;
    const __half* Qb = Q + headoff;
    const __half* Kb = K + headoff;
    const __half* Vb = V + headoff;

    const int tid = threadIdx.x;
    const int lane = tid & 31;
    const int warp = tid >> 5;
    const int g = lane >> 2;      // 0..7
    const int q4 = lane & 3;      // 0..3

    const uint32_t sQ = smem_u32(fsmh);
    const uint32_t sK0 = sQ + TILE_H * 2u;        // K buffers (reused for P)
    const uint32_t sV0 = sQ + 3u * TILE_H * 2u;   // V buffers

    // Q tile: 128 rows x 16 8-half chunks = 2048 slots, 8 per thread
#pragma unroll
    for (int i = 0; i < 8; ++i) {
        const int slot = tid + i * 256;
        const int r = slot >> 4, c = slot & 15;
        cp16(sQ + (uint32_t)(r * FP + c * 8) * 2u,
             Qb + (size_t)(q0 + r) * DMODEL + c * 8);
    }

    auto issue_kv = [&](int kt) {
        const int buf = kt & 1;
        const int k0 = kt * 128;
        const uint32_t dK = sK0 + (uint32_t)buf * TILE_H * 2u;
        const uint32_t dV = sV0 + (uint32_t)buf * TILE_H * 2u;
#pragma unroll
        for (int i = 0; i < 8; ++i) {
            const int slot = tid + i * 256;
            const int r = slot >> 4, c = slot & 15;
            cp16(dK + (uint32_t)(r * FP + c * 8) * 2u,
                 Kb + (size_t)(k0 + r) * DMODEL + c * 8);
            cp16(dV + (uint32_t)(r * FP + c * 8) * 2u,
                 Vb + (size_t)(k0 + r) * DMODEL + c * 8);
        }
        asm volatile("cp.async.commit_group;");
    };

    issue_kv(0);                       // group 0 = Q + KV0
    if (qt > 0) issue_kv(1);           // group 1 = KV1

    float m0 = -INFINITY, m1 = -INFINITY, l0 = 0.0f, l1 = 0.0f;
    float acco[16][4];
#pragma unroll
    for (int j = 0; j < 16; j++)
#pragma unroll
        for (int r = 0; r < 4; r++) acco[j][r] = 0.0f;

    const int ar = warp * 16 + g;   // local q row (first of the pair)

    // per-lane ldmatrix base offsets (bytes)
    const uint32_t qa_off =
        (uint32_t)((warp * 16 + (lane & 15)) * FP + ((lane >> 4) * 8)) * 2u;
    const uint32_t kb_off =
        (uint32_t)((lane & 7) * FP + (((lane >> 3) & 1) * 8)) * 2u;
    const uint32_t vt_off = (uint32_t)((lane & 15) * FP) * 2u;

    for (int kt = 0; kt <= qt; ++kt) {
        const int buf = kt & 1;
        const uint32_t sKc = sK0 + (uint32_t)buf * TILE_H * 2u;
        const uint32_t sVc = sV0 + (uint32_t)buf * TILE_H * 2u;

        if (kt < qt) {
            asm volatile("cp.async.wait_group 1;");
        } else {
            asm volatile("cp.async.wait_group 0;");
        }
        __syncthreads();

        // ---- S = Q @ K^T (scale folded into Q) ----
        float accs[16][4];
#pragma unroll
        for (int j = 0; j < 16; j++)
#pragma unroll
            for (int r = 0; r < 4; r++) accs[j][r] = 0.0f;

#pragma unroll
        for (int ks = 0; ks < 8; ++ks) {
            uint32_t a[4];
            ldsm4(a, sQ + qa_off + (uint32_t)(ks * 16) * 2u);
#pragma unroll
            for (int j = 0; j < 16; ++j) {
                uint32_t bb[2];
                ldsm2(bb, sKc + kb_off + (uint32_t)(j * 8 * FP + ks * 16) * 2u);
                mma_f16(accs[j], a, bb);
            }
        }

        // ---- causal mask (diagonal tile only) ----
        if (kt == qt) {
#pragma unroll
            for (int j = 0; j < 16; ++j) {
                const int c0 = j * 8 + 2 * q4;
                if (c0 > ar)          accs[j][0] = -1e30f;
                if (c0 + 1 > ar)      accs[j][1] = -1e30f;
                if (c0 > ar + 8)      accs[j][2] = -1e30f;
                if (c0 + 1 > ar + 8)  accs[j][3] = -1e30f;
            }
        }

        // ---- online softmax ----
        float mx0 = -INFINITY, mx1 = -INFINITY;
#pragma unroll
        for (int j = 0; j < 16; ++j) {
            mx0 = fmaxf(mx0, fmaxf(accs[j][0], accs[j][1]));
            mx1 = fmaxf(mx1, fmaxf(accs[j][2], accs[j][3]));
        }
        mx0 = fmaxf(mx0, __shfl_xor_sync(0xffffffffu, mx0, 1));
        mx0 = fmaxf(mx0, __shfl_xor_sync(0xffffffffu, mx0, 2));
        mx1 = fmaxf(mx1, __shfl_xor_sync(0xffffffffu, mx1, 1));
        mx1 = fmaxf(mx1, __shfl_xor_sync(0xffffffffu, mx1, 2));
        const float mn0 = fmaxf(m0, mx0);
        const float mn1 = fmaxf(m1, mx1);
        const float cr0 = __expf(m0 - mn0);
        const float cr1 = __expf(m1 - mn1);
        float s0 = 0.0f, s1 = 0.0f;
#pragma unroll
        for (int j = 0; j < 16; ++j) {
            accs[j][0] = __expf(accs[j][0] - mn0); s0 += accs[j][0];
            accs[j][1] = __expf(accs[j][1] - mn0); s0 += accs[j][1];
            accs[j][2] = __expf(accs[j][2] - mn1); s1 += accs[j][2];
            accs[j][3] = __expf(accs[j][3] - mn1); s1 += accs[j][3];
        }
        s0 += __shfl_xor_sync(0xffffffffu, s0, 1);
        s0 += __shfl_xor_sync(0xffffffffu, s0, 2);
        s1 += __shfl_xor_sync(0xffffffffu, s1, 1);
        s1 += __shfl_xor_sync(0xffffffffu, s1, 2);
        l0 = l0 * cr0 + s0;  m0 = mn0;
        l1 = l1 * cr1 + s1;  m1 = mn1;
#pragma unroll
        for (int j = 0; j < 16; ++j) {
            acco[j][0] *= cr0; acco[j][1] *= cr0;
            acco[j][2] *= cr1; acco[j][3] *= cr1;
        }

        // ---- spill P (fp16) into the K buffer ----
        __syncthreads();   // all warps done reading K[buf]
        __half* Ph = (__half*)((char*)fsmh + (sKc - sQ));
#pragma unroll
        for (int j = 0; j < 16; ++j) {
            *(__half2*)(Ph + ar * FP + j * 8 + 2 * q4) =
                __floats2half2_rn(accs[j][0], accs[j][1]);
            *(__half2*)(Ph + (ar + 8) * FP + j * 8 + 2 * q4) =
                __floats2half2_rn(accs[j][2], accs[j][3]);
        }
        __syncwarp();

        // ---- O += P @ V  (V via ldmatrix.trans) ----
#pragma unroll
        for (int ks = 0; ks < 8; ++ks) {
            uint32_t a[4];
            ldsm4(a, sKc + qa_off + (uint32_t)(ks * 16) * 2u);
#pragma unroll
            for (int j = 0; j < 16; ++j) {
                uint32_t bb[2];
                ldsm2t(bb, sVc + vt_off + (uint32_t)(ks * 16 * FP + j * 8) * 2u);
                mma_f16(acco[j], a, bb);
            }
        }

        __syncthreads();   // all warps done reading V[buf] (and P)
        if (kt + 2 <= qt) issue_kv(kt + 2);
    }

    // ---- normalize + store fp16 ----
    const float i0 = 1.0f / l0;
    const float i1 = 1.0f / l1;
#pragma unroll
    for (int j = 0; j < 16; ++j) {
        *(__half2*)(O + headoff + (size_t)(q0 + ar) * DMODEL + j * 8 + 2 * q4) =
            __floats2half2_rn(acco[j][0] * i0, acco[j][1] * i0);
        *(__half2*)(O + headoff + (size_t)(q0 + ar + 8) * DMODEL + j * 8 + 2 * q4) =
            __floats2half2_rn(acco[j][2] * i1, acco[j][3] * i1);
    }
}

// ---------------------------------------------------------------------------
extern "C" void kernel_launch(void* const* d_in, const int* in_sizes, int n_in,
                              void* d_out, int out_size)
{
    const float* query = (const float*)d_in[0];
    const float* key_i = (const float*)d_in[1];
    const float* value = (const float*)d_in[2];
    const float* Wq = (const float*)d_in[3];
    const float* bq = (const float*)d_in[4];
    const float* Wk = (const float*)d_in[5];
    const float* bk = (const float*)d_in[6];
    const float* Wv = (const float*)d_in[7];
    const float* bv = (const float*)d_in[8];
    const float* Wo = (const float*)d_in[9];
    const float* bo = (const float*)d_in[10];
    float* out = (float*)d_out;

    __half *xq, *xk, *xv, *wq, *wk, *wv, *wo, *pq, *pk, *pv, *pa;
    cudaGetSymbolAddress((void**)&xq, hx_q);
    cudaGetSymbolAddress((void**)&xk, hx_k);
    cudaGetSymbolAddress((void**)&xv, hx_v);
    cudaGetSymbolAddress((void**)&wq, hw_q);
    cudaGetSymbolAddress((void**)&wk, hw_k);
    cudaGetSymbolAddress((void**)&wv, hw_v);
    cudaGetSymbolAddress((void**)&wo, hw_o);
    cudaGetSymbolAddress((void**)&pq, h_q);
    cudaGetSymbolAddress((void**)&pk, h_k);
    cudaGetSymbolAddress((void**)&pv, h_v);
    cudaGetSymbolAddress((void**)&pa, h_a);

    const int act4 = (MROWS * DMODEL) / 4;
    const int w4 = (DMODEL * DMODEL) / 4;
    f32_to_f16_k<<<(act4 + 255) / 256, 256>>>((const float4*)query, (uint2*)xq, act4);
    f32_to_f16_k<<<(act4 + 255) / 256, 256>>>((const float4*)key_i, (uint2*)xk, act4);
    f32_to_f16_k<<<(act4 + 255) / 256, 256>>>((const float4*)value, (uint2*)xv, act4);
    f32_to_f16_k<<<(w4 + 255) / 256, 256>>>((const float4*)Wq, (uint2*)wq, w4);
    f32_to_f16_k<<<(w4 + 255) / 256, 256>>>((const float4*)Wk, (uint2*)wk, w4);
    f32_to_f16_k<<<(w4 + 255) / 256, 256>>>((const float4*)Wv, (uint2*)wv, w4);
    f32_to_f16_k<<<(w4 + 255) / 256, 256>>>((const float4*)Wo, (uint2*)wo, w4);

    cudaFuncSetAttribute(gemm_tc, cudaFuncAttributeMaxDynamicSharedMemorySize,
                         GEMM_SMEM);
    const dim3 ggrid(GN / TBN, MROWS / TBM);  // (8, 32)

    gemm_tc<<<ggrid, 256, GEMM_SMEM>>>(xq, wq, bq, pq, ATT_SCALE, 1);
    gemm_tc<<<ggrid, 256, GEMM_SMEM>>>(xk, wk, bk, pk, 1.0f, 1);
    gemm_tc<<<ggrid, 256, GEMM_SMEM>>>(xv, wv, bv, pv, 1.0f, 1);

    cudaFuncSetAttribute(flash_tc, cudaFuncAttributeMaxDynamicSharedMemorySize,
                         FLASH_SMEM);
    const dim3 agrid(SEQ / 128, NHEAD, BATCH);
    flash_tc<<<agrid, 256, FLASH_SMEM>>>(pq, pk, pv, pa);

    gemm_tc<<<ggrid, 256, GEMM_SMEM>>>(pa, wo, bo, out, 1.0f, 0);
}

// round 6
// speedup vs baseline: 7.2809x; 1.0412x over previous
#include <cuda_runtime.h>
#include <cuda_fp16.h>
#include <math.h>
#include <stdint.h>

#define BATCH 2
#define SEQ 2048
#define DMODEL 2048
#define NHEAD 16
#define HDIM 128
#define MROWS (BATCH * SEQ)          // 4096
#define ATT_SCALE 0.08838834764831845f  // 1/sqrt(128)

// Scratch (device globals: allocation-free per harness rules)
__device__ __half hx_q[(size_t)MROWS * DMODEL];   // fp16 inputs
__device__ __half hx_k[(size_t)MROWS * DMODEL];
__device__ __half hx_v[(size_t)MROWS * DMODEL];
__device__ __half hw_q[(size_t)DMODEL * DMODEL];  // fp16 weights
__device__ __half hw_k[(size_t)DMODEL * DMODEL];
__device__ __half hw_v[(size_t)DMODEL * DMODEL];
__device__ __half hw_o[(size_t)DMODEL * DMODEL];
__device__ __half h_q[(size_t)MROWS * DMODEL];    // projected q (pre-scaled)
__device__ __half h_k[(size_t)MROWS * DMODEL];
__device__ __half h_v[(size_t)MROWS * DMODEL];
__device__ __half h_a[(size_t)MROWS * DMODEL];    // attention output

// ===========================================================================
// helpers
// ===========================================================================
__device__ __forceinline__ uint32_t smem_u32(const void* p) {
    uint32_t a;
    asm("{ .reg .u64 t; cvta.to.shared.u64 t, %1; cvt.u32.u64 %0, t; }"
        : "=r"(a) : "l"(p));
    return a;
}

__device__ __forceinline__ void cp16(uint32_t dst, const void* src) {
    asm volatile("cp.async.cg.shared.global [%0], [%1], 16;"
                 :: "r"(dst), "l"(src));
}

__device__ __forceinline__ void mma_f16(float* d, const uint32_t* a,
                                        const uint32_t* b)
{
    asm volatile(
        "mma.sync.aligned.m16n8k16.row.col.f32.f16.f16.f32 "
        "{%0,%1,%2,%3}, {%4,%5,%6,%7}, {%8,%9}, {%0,%1,%2,%3};"
        : "+f"(d[0]), "+f"(d[1]), "+f"(d[2]), "+f"(d[3])
        : "r"(a[0]), "r"(a[1]), "r"(a[2]), "r"(a[3]),
          "r"(b[0]), "r"(b[1]));
}

__device__ __forceinline__ void ldsm4(uint32_t* r, uint32_t a) {
    asm volatile("ldmatrix.sync.aligned.m8n8.x4.shared.b16 {%0,%1,%2,%3}, [%4];"
                 : "=r"(r[0]), "=r"(r[1]), "=r"(r[2]), "=r"(r[3]) : "r"(a));
}
__device__ __forceinline__ void ldsm2(uint32_t* r, uint32_t a) {
    asm volatile("ldmatrix.sync.aligned.m8n8.x2.shared.b16 {%0,%1}, [%2];"
                 : "=r"(r[0]), "=r"(r[1]) : "r"(a));
}
__device__ __forceinline__ void ldsm4t(uint32_t* r, uint32_t a) {
    asm volatile("ldmatrix.sync.aligned.m8n8.x4.trans.shared.b16 {%0,%1,%2,%3}, [%4];"
                 : "=r"(r[0]), "=r"(r[1]), "=r"(r[2]), "=r"(r[3]) : "r"(a));
}

__device__ __forceinline__ uint32_t pack_h2(float x, float y) {
    __half2 h = __floats2half2_rn(x, y);
    return *(uint32_t*)&h;
}

// ===========================================================================
// merged fp32 -> fp16 conversion passes
// ===========================================================================
__device__ __forceinline__ uint2 cvt4(float4 v) {
    union { __half2 h[2]; uint2 u; } p;
    p.h[0] = __floats2half2_rn(v.x, v.y);
    p.h[1] = __floats2half2_rn(v.z, v.w);
    return p.u;
}

__global__ void conv_act(const float4* __restrict__ q,
                         const float4* __restrict__ k,
                         const float4* __restrict__ v,
                         uint2* __restrict__ oq, uint2* __restrict__ ok,
                         uint2* __restrict__ ov, int n4)
{
    int i = blockIdx.x * blockDim.x + threadIdx.x;
    if (i >= n4) return;
    const float4* src = (blockIdx.y == 0) ? q : (blockIdx.y == 1) ? k : v;
    uint2* dst = (blockIdx.y == 0) ? oq : (blockIdx.y == 1) ? ok : ov;
    dst[i] = cvt4(src[i]);
}

__global__ void conv_w(const float4* __restrict__ w0,
                       const float4* __restrict__ w1,
                       const float4* __restrict__ w2,
                       const float4* __restrict__ w3,
                       uint2* __restrict__ o0, uint2* __restrict__ o1,
                       uint2* __restrict__ o2, uint2* __restrict__ o3, int n4)
{
    int i = blockIdx.x * blockDim.x + threadIdx.x;
    if (i >= n4) return;
    const float4* src = (blockIdx.y == 0) ? w0 : (blockIdx.y == 1) ? w1
                      : (blockIdx.y == 2) ? w2 : w3;
    uint2* dst = (blockIdx.y == 0) ? o0 : (blockIdx.y == 1) ? o1
               : (blockIdx.y == 2) ? o2 : o3;
    dst[i] = cvt4(src[i]);
}

// ===========================================================================
// fp16 mma.sync GEMM: C[M,2048] = A[M,2048] @ W[2048,2048]^T + bias
// CTA tile 128x256, BK=64 halves, 3-stage cp.async, 8 warps (64x64 each).
// ===========================================================================
#define TBM 128
#define TBN 256
#define GK 2048
#define GN 2048
#define GBKH 64
#define AP 72
#define ASTGH (TBM * AP)
#define BSTGH (TBN * AP)
#define STGH (ASTGH + BSTGH)
#define GEMM_SMEM (3 * STGH * 2)      // 165888 B
#define NT (GK / GBKH)                // 32

__global__ __launch_bounds__(256, 1)
void gemm_tc(const __half* __restrict__ A, const __half* __restrict__ W,
             const float* __restrict__ bias, void* __restrict__ Cout,
             float scale, int half_out)
{
    extern __shared__ __half gsmh[];

    const int tid = threadIdx.x;
    const int lane = tid & 31;
    const int warp = tid >> 5;
    const int wm = warp & 1;
    const int wn = warp >> 1;
    const int m0 = blockIdx.y * TBM;
    const int n0 = blockIdx.x * TBN;

    const uint32_t sbase = smem_u32(gsmh);
    const int cr = tid >> 3;
    const int cc = tid & 7;

    float acc[4][8][4];
#pragma unroll
    for (int i = 0; i < 4; i++)
#pragma unroll
        for (int j = 0; j < 8; j++)
#pragma unroll
            for (int r = 0; r < 4; r++) acc[i][j][r] = 0.0f;

    auto issue = [&](int t, int buf) {
        const __half* Ab = A + (size_t)m0 * GK + t * GBKH;
        const __half* Wb = W + (size_t)n0 * GK + t * GBKH;
        const uint32_t sa = sbase + (uint32_t)buf * STGH * 2u;
        const uint32_t sb = sa + ASTGH * 2u;
#pragma unroll
        for (int i = 0; i < 4; i++) {
            const int r = cr + i * 32;
            cp16(sa + (uint32_t)(r * AP + cc * 8) * 2u,
                 Ab + (size_t)r * GK + cc * 8);
        }
#pragma unroll
        for (int i = 0; i < 8; i++) {
            const int r = cr + i * 32;
            cp16(sb + (uint32_t)(r * AP + cc * 8) * 2u,
                 Wb + (size_t)r * GK + cc * 8);
        }
        asm volatile("cp.async.commit_group;");
    };

    issue(0, 0);
    issue(1, 1);

    const uint32_t a_lane_off =
        (uint32_t)((wm * 64 + (lane & 15)) * AP + ((lane >> 4) * 8)) * 2u;
    // B x4: n16 x k16 fragments
    const uint32_t b4_lane_off =
        (uint32_t)((wn * 64 + (lane & 7) + ((lane >> 4) & 1) * 8) * AP
                   + (((lane >> 3) & 1) * 8)) * 2u;

    for (int t = 0; t < NT; ++t) {
        if (t + 1 < NT) {
            asm volatile("cp.async.wait_group 1;");
        } else {
            asm volatile("cp.async.wait_group 0;");
        }
        __syncthreads();
        if (t + 2 < NT) issue(t + 2, (t + 2) % 3);

        const uint32_t sa = sbase + (uint32_t)(t % 3) * STGH * 2u;
        const uint32_t sb = sa + ASTGH * 2u;
        const uint32_t aaddr = sa + a_lane_off;
        const uint32_t baddr = sb + b4_lane_off;

#pragma unroll
        for (int ks = 0; ks < 4; ++ks) {
            uint32_t a[4][4], b[4][4];
#pragma unroll
            for (int ms = 0; ms < 4; ms++)
                ldsm4(a[ms], aaddr + (uint32_t)(ms * 16 * AP + ks * 16) * 2u);
#pragma unroll
            for (int np = 0; np < 4; np++)
                ldsm4(b[np], baddr + (uint32_t)(np * 16 * AP + ks * 16) * 2u);
#pragma unroll
            for (int ms = 0; ms < 4; ms++)
#pragma unroll
                for (int np = 0; np < 4; np++) {
                    mma_f16(acc[ms][np * 2], a[ms], b[np]);
                    mma_f16(acc[ms][np * 2 + 1], a[ms], b[np] + 2);
                }
        }
    }

    float2 bv[8];
#pragma unroll
    for (int ns = 0; ns < 8; ns++) {
        const int col = n0 + wn * 64 + ns * 8 + 2 * (lane & 3);
        bv[ns] = *(const float2*)(bias + col);
    }

    if (half_out) {
        __half* C = (__half*)Cout;
#pragma unroll
        for (int ms = 0; ms < 4; ms++) {
            const int row0 = m0 + wm * 64 + ms * 16 + (lane >> 2);
#pragma unroll
            for (int ns = 0; ns < 8; ns++) {
                const int col = n0 + wn * 64 + ns * 8 + 2 * (lane & 3);
                __half2 v0 = __floats2half2_rn((acc[ms][ns][0] + bv[ns].x) * scale,
                                               (acc[ms][ns][1] + bv[ns].y) * scale);
                __half2 v1 = __floats2half2_rn((acc[ms][ns][2] + bv[ns].x) * scale,
                                               (acc[ms][ns][3] + bv[ns].y) * scale);
                *(__half2*)(C + (size_t)row0 * GN + col) = v0;
                *(__half2*)(C + (size_t)(row0 + 8) * GN + col) = v1;
            }
        }
    } else {
        float* C = (float*)Cout;
#pragma unroll
        for (int ms = 0; ms < 4; ms++) {
            const int row0 = m0 + wm * 64 + ms * 16 + (lane >> 2);
#pragma unroll
            for (int ns = 0; ns < 8; ns++) {
                const int col = n0 + wn * 64 + ns * 8 + 2 * (lane & 3);
                float2 v0 = make_float2(acc[ms][ns][0] + bv[ns].x,
                                        acc[ms][ns][1] + bv[ns].y);
                float2 v1 = make_float2(acc[ms][ns][2] + bv[ns].x,
                                        acc[ms][ns][3] + bv[ns].y);
                *(float2*)(C + (size_t)row0 * GN + col) = v0;
                *(float2*)(C + (size_t)(row0 + 8) * GN + col) = v1;
            }
        }
    }
}

// ===========================================================================
// fp16 flash attention v2: register-resident P, ldsm x4, Q frags hoisted.
// One CTA per (b, h, 128-row q tile); 8 warps, warp owns 16 q rows.
// ===========================================================================
#define FP 136
#define TILE_H (128 * FP)
#define FLASH_SMEM (TILE_H * 2 * 5)   // Q + 2K + 2V = 174080 B

__global__ __launch_bounds__(256, 1)
void flash_tc(const __half* __restrict__ Q, const __half* __restrict__ K,
              const __half* __restrict__ V, __half* __restrict__ O)
{
    extern __shared__ __half fsmh[];

    const int qt = (SEQ / 128) - 1 - blockIdx.x;   // heavy tiles first
    const int h = blockIdx.y;
    const int b = blockIdx.z;
    const int q0 = qt * 128;
    const size_t headoff = (size_t)b * SEQ * DMODEL + (size_t)h * HDIM;
    const __half* Qb = Q + headoff;
    const __half* Kb = K + headoff;
    const __half* Vb = V + headoff;

    const int tid = threadIdx.x;
    const int lane = tid & 31;
    const int warp = tid >> 5;
    const int g = lane >> 2;
    const int q4 = lane & 3;

    const uint32_t sQ = smem_u32(fsmh);
    const uint32_t sK0 = sQ + TILE_H * 2u;
    const uint32_t sV0 = sQ + 3u * TILE_H * 2u;

    // Q tile load
#pragma unroll
    for (int i = 0; i < 8; ++i) {
        const int slot = tid + i * 256;
        const int r = slot >> 4, c = slot & 15;
        cp16(sQ + (uint32_t)(r * FP + c * 8) * 2u,
             Qb + (size_t)(q0 + r) * DMODEL + c * 8);
    }

    auto issue_kv = [&](int kt) {
        const int buf = kt & 1;
        const int k0 = kt * 128;
        const uint32_t dK = sK0 + (uint32_t)buf * TILE_H * 2u;
        const uint32_t dV = sV0 + (uint32_t)buf * TILE_H * 2u;
#pragma unroll
        for (int i = 0; i < 8; ++i) {
            const int slot = tid + i * 256;
            const int r = slot >> 4, c = slot & 15;
            cp16(dK + (uint32_t)(r * FP + c * 8) * 2u,
                 Kb + (size_t)(k0 + r) * DMODEL + c * 8);
            cp16(dV + (uint32_t)(r * FP + c * 8) * 2u,
                 Vb + (size_t)(k0 + r) * DMODEL + c * 8);
        }
        asm volatile("cp.async.commit_group;");
    };

    issue_kv(0);
    if (qt > 0) issue_kv(1);

    float m0 = -INFINITY, m1 = -INFINITY, l0 = 0.0f, l1 = 0.0f;
    float acco[16][4];
#pragma unroll
    for (int j = 0; j < 16; j++)
#pragma unroll
        for (int r = 0; r < 4; r++) acco[j][r] = 0.0f;

    const int ar = warp * 16 + g;

    // per-lane ldmatrix offsets (bytes)
    const uint32_t qa_off =
        (uint32_t)((warp * 16 + (lane & 15)) * FP + ((lane >> 4) * 8)) * 2u;
    // K x4 (n16 x k16, non-trans)
    const uint32_t kb4_off =
        (uint32_t)(((lane & 7) + ((lane >> 4) & 1) * 8) * FP
                   + (((lane >> 3) & 1) * 8)) * 2u;
    // V x4 trans (n16 x k16)
    const uint32_t vt4_off =
        (uint32_t)(((lane & 7) + ((lane >> 3) & 1) * 8) * FP
                   + ((lane >> 4) * 8)) * 2u;

    uint32_t qf[8][4];
    bool qloaded = false;

    for (int kt = 0; kt <= qt; ++kt) {
        const int buf = kt & 1;
        const uint32_t sKc = sK0 + (uint32_t)buf * TILE_H * 2u;
        const uint32_t sVc = sV0 + (uint32_t)buf * TILE_H * 2u;

        if (kt < qt) {
            asm volatile("cp.async.wait_group 1;");
        } else {
            asm volatile("cp.async.wait_group 0;");
        }
        __syncthreads();

        if (!qloaded) {
#pragma unroll
            for (int ks = 0; ks < 8; ++ks)
                ldsm4(qf[ks], sQ + qa_off + (uint32_t)(ks * 16) * 2u);
            qloaded = true;
        }

        // ---- S = Q @ K^T ----
        float accs[16][4];
#pragma unroll
        for (int j = 0; j < 16; j++)
#pragma unroll
            for (int r = 0; r < 4; r++) accs[j][r] = 0.0f;

#pragma unroll
        for (int ks = 0; ks < 8; ++ks) {
#pragma unroll
            for (int jp = 0; jp < 8; ++jp) {
                uint32_t bb[4];
                ldsm4(bb, sKc + kb4_off + (uint32_t)(jp * 16 * FP + ks * 16) * 2u);
                mma_f16(accs[jp * 2], qf[ks], bb);
                mma_f16(accs[jp * 2 + 1], qf[ks], bb + 2);
            }
        }

        // ---- causal mask (diagonal tile only) ----
        if (kt == qt) {
#pragma unroll
            for (int j = 0; j < 16; ++j) {
                const int c0 = j * 8 + 2 * q4;
                if (c0 > ar)          accs[j][0] = -1e30f;
                if (c0 + 1 > ar)      accs[j][1] = -1e30f;
                if (c0 > ar + 8)      accs[j][2] = -1e30f;
                if (c0 + 1 > ar + 8)  accs[j][3] = -1e30f;
            }
        }

        // ---- online softmax ----
        float mx0 = -INFINITY, mx1 = -INFINITY;
#pragma unroll
        for (int j = 0; j < 16; ++j) {
            mx0 = fmaxf(mx0, fmaxf(accs[j][0], accs[j][1]));
            mx1 = fmaxf(mx1, fmaxf(accs[j][2], accs[j][3]));
        }
        mx0 = fmaxf(mx0, __shfl_xor_sync(0xffffffffu, mx0, 1));
        mx0 = fmaxf(mx0, __shfl_xor_sync(0xffffffffu, mx0, 2));
        mx1 = fmaxf(mx1, __shfl_xor_sync(0xffffffffu, mx1, 1));
        mx1 = fmaxf(mx1, __shfl_xor_sync(0xffffffffu, mx1, 2));
        const float mn0 = fmaxf(m0, mx0);
        const float mn1 = fmaxf(m1, mx1);
        const float cr0 = __expf(m0 - mn0);
        const float cr1 = __expf(m1 - mn1);
        float s0 = 0.0f, s1 = 0.0f;
#pragma unroll
        for (int j = 0; j < 16; ++j) {
            accs[j][0] = __expf(accs[j][0] - mn0); s0 += accs[j][0];
            accs[j][1] = __expf(accs[j][1] - mn0); s0 += accs[j][1];
            accs[j][2] = __expf(accs[j][2] - mn1); s1 += accs[j][2];
            accs[j][3] = __expf(accs[j][3] - mn1); s1 += accs[j][3];
        }
        s0 += __shfl_xor_sync(0xffffffffu, s0, 1);
        s0 += __shfl_xor_sync(0xffffffffu, s0, 2);
        s1 += __shfl_xor_sync(0xffffffffu, s1, 1);
        s1 += __shfl_xor_sync(0xffffffffu, s1, 2);
        l0 = l0 * cr0 + s0;  m0 = mn0;
        l1 = l1 * cr1 + s1;  m1 = mn1;
#pragma unroll
        for (int j = 0; j < 16; ++j) {
            acco[j][0] *= cr0; acco[j][1] *= cr0;
            acco[j][2] *= cr1; acco[j][3] *= cr1;
        }

        // ---- O += P @ V : P stays in registers (C-frag == A-frag layout) ----
#pragma unroll
        for (int t = 0; t < 8; ++t) {
            uint32_t a[4];
            a[0] = pack_h2(accs[2 * t][0], accs[2 * t][1]);
            a[1] = pack_h2(accs[2 * t][2], accs[2 * t][3]);
            a[2] = pack_h2(accs[2 * t + 1][0], accs[2 * t + 1][1]);
            a[3] = pack_h2(accs[2 * t + 1][2], accs[2 * t + 1][3]);
#pragma unroll
            for (int jp = 0; jp < 8; ++jp) {
                uint32_t bb[4];
                ldsm4t(bb, sVc + vt4_off + (uint32_t)(t * 16 * FP + jp * 16) * 2u);
                mma_f16(acco[jp * 2], a, bb);
                mma_f16(acco[jp * 2 + 1], a, bb + 2);
            }
        }

        __syncthreads();   // all warps done with K/V[buf] before overwrite
        if (kt + 2 <= qt) issue_kv(kt + 2);
    }

    // ---- normalize + store fp16 ----
    const float i0 = 1.0f / l0;
    const float i1 = 1.0f / l1;
#pragma unroll
    for (int j = 0; j < 16; ++j) {
        *(__half2*)(O + headoff + (size_t)(q0 + ar) * DMODEL + j * 8 + 2 * q4) =
            __floats2half2_rn(acco[j][0] * i0, acco[j][1] * i0);
        *(__half2*)(O + headoff + (size_t)(q0 + ar + 8) * DMODEL + j * 8 + 2 * q4) =
            __floats2half2_rn(acco[j][2] * i1, acco[j][3] * i1);
    }
}

// ---------------------------------------------------------------------------
extern "C" void kernel_launch(void* const* d_in, const int* in_sizes, int n_in,
                              void* d_out, int out_size)
{
    const float* query = (const float*)d_in[0];
    const float* key_i = (const float*)d_in[1];
    const float* value = (const float*)d_in[2];
    const float* Wq = (const float*)d_in[3];
    const float* bq = (const float*)d_in[4];
    const float* Wk = (const float*)d_in[5];
    const float* bk = (const float*)d_in[6];
    const float* Wv = (const float*)d_in[7];
    const float* bv = (const float*)d_in[8];
    const float* Wo = (const float*)d_in[9];
    const float* bo = (const float*)d_in[10];
    float* out = (float*)d_out;

    __half *xq, *xk, *xv, *wq, *wk, *wv, *wo, *pq, *pk, *pv, *pa;
    cudaGetSymbolAddress((void**)&xq, hx_q);
    cudaGetSymbolAddress((void**)&xk, hx_k);
    cudaGetSymbolAddress((void**)&xv, hx_v);
    cudaGetSymbolAddress((void**)&wq, hw_q);
    cudaGetSymbolAddress((void**)&wk, hw_k);
    cudaGetSymbolAddress((void**)&wv, hw_v);
    cudaGetSymbolAddress((void**)&wo, hw_o);
    cudaGetSymbolAddress((void**)&pq, h_q);
    cudaGetSymbolAddress((void**)&pk, h_k);
    cudaGetSymbolAddress((void**)&pv, h_v);
    cudaGetSymbolAddress((void**)&pa, h_a);

    const int act4 = (MROWS * DMODEL) / 4;
    const int w4 = (DMODEL * DMODEL) / 4;
    conv_act<<<dim3((act4 + 255) / 256, 3), 256>>>(
        (const float4*)query, (const float4*)key_i, (const float4*)value,
        (uint2*)xq, (uint2*)xk, (uint2*)xv, act4);
    conv_w<<<dim3((w4 + 255) / 256, 4), 256>>>(
        (const float4*)Wq, (const float4*)Wk, (const float4*)Wv,
        (const float4*)Wo, (uint2*)wq, (uint2*)wk, (uint2*)wv, (uint2*)wo, w4);

    cudaFuncSetAttribute(gemm_tc, cudaFuncAttributeMaxDynamicSharedMemorySize,
                         GEMM_SMEM);
    const dim3 ggrid(GN / TBN, MROWS / TBM);  // (8, 32)

    gemm_tc<<<ggrid, 256, GEMM_SMEM>>>(xq, wq, bq, pq, ATT_SCALE, 1);
    gemm_tc<<<ggrid, 256, GEMM_SMEM>>>(xk, wk, bk, pk, 1.0f, 1);
    gemm_tc<<<ggrid, 256, GEMM_SMEM>>>(xv, wv, bv, pv, 1.0f, 1);

    cudaFuncSetAttribute(flash_tc, cudaFuncAttributeMaxDynamicSharedMemorySize,
                         FLASH_SMEM);
    const dim3 agrid(SEQ / 128, NHEAD, BATCH);
    flash_tc<<<agrid, 256, FLASH_SMEM>>>(pq, pk, pv, pa);   // 6th launch -> ncu

    gemm_tc<<<ggrid, 256, GEMM_SMEM>>>(pa, wo, bo, out, 1.0f, 0);
}

// round 7
// speedup vs baseline: 7.3851x; 1.0143x over previous
#include <cuda_runtime.h>
#include <cuda_fp16.h>
#include <math.h>
#include <stdint.h>

#define BATCH 2
#define SEQ 2048
#define DMODEL 2048
#define NHEAD 16
#define HDIM 128
#define MROWS (BATCH * SEQ)          // 4096
#define ATT_SCALE 0.08838834764831845f  // 1/sqrt(128)

// Scratch (device globals: allocation-free per harness rules)
__device__ __half hx_q[(size_t)MROWS * DMODEL];   // fp16 inputs
__device__ __half hx_k[(size_t)MROWS * DMODEL];
__device__ __half hx_v[(size_t)MROWS * DMODEL];
__device__ __half hw_q[(size_t)DMODEL * DMODEL];  // fp16 weights
__device__ __half hw_k[(size_t)DMODEL * DMODEL];
__device__ __half hw_v[(size_t)DMODEL * DMODEL];
__device__ __half hw_o[(size_t)DMODEL * DMODEL];
__device__ __half h_q[(size_t)MROWS * DMODEL];    // projected q (pre-scaled)
__device__ __half h_k[(size_t)MROWS * DMODEL];
__device__ __half h_v[(size_t)MROWS * DMODEL];
__device__ __half h_a[(size_t)MROWS * DMODEL];    // attention output

// ===========================================================================
// helpers
// ===========================================================================
__device__ __forceinline__ uint32_t smem_u32(const void* p) {
    uint32_t a;
    asm("{ .reg .u64 t; cvta.to.shared.u64 t, %1; cvt.u32.u64 %0, t; }"
        : "=r"(a) : "l"(p));
    return a;
}

__device__ __forceinline__ void cp16(uint32_t dst, const void* src) {
    asm volatile("cp.async.cg.shared.global [%0], [%1], 16;"
                 :: "r"(dst), "l"(src));
}

__device__ __forceinline__ void mma_f16(float* d, const uint32_t* a,
                                        const uint32_t* b)
{
    asm volatile(
        "mma.sync.aligned.m16n8k16.row.col.f32.f16.f16.f32 "
        "{%0,%1,%2,%3}, {%4,%5,%6,%7}, {%8,%9}, {%0,%1,%2,%3};"
        : "+f"(d[0]), "+f"(d[1]), "+f"(d[2]), "+f"(d[3])
        : "r"(a[0]), "r"(a[1]), "r"(a[2]), "r"(a[3]),
          "r"(b[0]), "r"(b[1]));
}

__device__ __forceinline__ void ldsm4(uint32_t* r, uint32_t a) {
    asm volatile("ldmatrix.sync.aligned.m8n8.x4.shared.b16 {%0,%1,%2,%3}, [%4];"
                 : "=r"(r[0]), "=r"(r[1]), "=r"(r[2]), "=r"(r[3]) : "r"(a));
}
__device__ __forceinline__ void ldsm4t(uint32_t* r, uint32_t a) {
    asm volatile("ldmatrix.sync.aligned.m8n8.x4.trans.shared.b16 {%0,%1,%2,%3}, [%4];"
                 : "=r"(r[0]), "=r"(r[1]), "=r"(r[2]), "=r"(r[3]) : "r"(a));
}

__device__ __forceinline__ uint32_t pack_h2(float x, float y) {
    __half2 h = __floats2half2_rn(x, y);
    return *(uint32_t*)&h;
}

// ===========================================================================
// merged fp32 -> fp16 conversion passes
// ===========================================================================
__device__ __forceinline__ uint2 cvt4(float4 v) {
    union { __half2 h[2]; uint2 u; } p;
    p.h[0] = __floats2half2_rn(v.x, v.y);
    p.h[1] = __floats2half2_rn(v.z, v.w);
    return p.u;
}

__global__ void conv_act(const float4* __restrict__ q,
                         const float4* __restrict__ k,
                         const float4* __restrict__ v,
                         uint2* __restrict__ oq, uint2* __restrict__ ok,
                         uint2* __restrict__ ov, int n4)
{
    int i = blockIdx.x * blockDim.x + threadIdx.x;
    if (i >= n4) return;
    const float4* src = (blockIdx.y == 0) ? q : (blockIdx.y == 1) ? k : v;
    uint2* dst = (blockIdx.y == 0) ? oq : (blockIdx.y == 1) ? ok : ov;
    dst[i] = cvt4(src[i]);
}

__global__ void conv_w(const float4* __restrict__ w0,
                       const float4* __restrict__ w1,
                       const float4* __restrict__ w2,
                       const float4* __restrict__ w3,
                       uint2* __restrict__ o0, uint2* __restrict__ o1,
                       uint2* __restrict__ o2, uint2* __restrict__ o3, int n4)
{
    int i = blockIdx.x * blockDim.x + threadIdx.x;
    if (i >= n4) return;
    const float4* src = (blockIdx.y == 0) ? w0 : (blockIdx.y == 1) ? w1
                      : (blockIdx.y == 2) ? w2 : w3;
    uint2* dst = (blockIdx.y == 0) ? o0 : (blockIdx.y == 1) ? o1
               : (blockIdx.y == 2) ? o2 : o3;
    dst[i] = cvt4(src[i]);
}

// ===========================================================================
// fp16 mma.sync GEMM core: C[M,2048] = A[M,2048] @ W[2048,2048]^T + bias
// CTA tile 128x256, BK=64 halves, 3-stage cp.async, 512 threads / 16 warps,
// warp tile 32x64, register-double-buffered fragments.
// ===========================================================================
#define TBM 128
#define TBN 256
#define GK 2048
#define GN 2048
#define GBKH 64
#define AP 72
#define ASTGH (TBM * AP)
#define BSTGH (TBN * AP)
#define STGH (ASTGH + BSTGH)
#define GEMM_SMEM (3 * STGH * 2)      // 165888 B
#define NT (GK / GBKH)                // 32

__device__ __forceinline__ void gemm_core(
    const __half* __restrict__ A, const __half* __restrict__ W,
    const float* __restrict__ bias, void* __restrict__ Cout,
    float scale, int half_out, int bx, int by)
{
    extern __shared__ __half gsmh[];

    const int tid = threadIdx.x;
    const int lane = tid & 31;
    const int warp = tid >> 5;        // 0..15
    const int wm = warp & 3;          // 4 m-slots of 32
    const int wn = warp >> 2;         // 4 n-slots of 64
    const int m0 = by * TBM;
    const int n0 = bx * TBN;

    const uint32_t sbase = smem_u32(gsmh);
    const int cr = tid >> 3;          // 0..63
    const int cc = tid & 7;

    float acc[2][8][4];
#pragma unroll
    for (int i = 0; i < 2; i++)
#pragma unroll
        for (int j = 0; j < 8; j++)
#pragma unroll
            for (int r = 0; r < 4; r++) acc[i][j][r] = 0.0f;

    auto issue = [&](int t, int buf) {
        const __half* Ab = A + (size_t)m0 * GK + t * GBKH;
        const __half* Wb = W + (size_t)n0 * GK + t * GBKH;
        const uint32_t sa = sbase + (uint32_t)buf * STGH * 2u;
        const uint32_t sb = sa + ASTGH * 2u;
#pragma unroll
        for (int i = 0; i < 2; i++) {
            const int r = cr + i * 64;
            cp16(sa + (uint32_t)(r * AP + cc * 8) * 2u,
                 Ab + (size_t)r * GK + cc * 8);
        }
#pragma unroll
        for (int i = 0; i < 4; i++) {
            const int r = cr + i * 64;
            cp16(sb + (uint32_t)(r * AP + cc * 8) * 2u,
                 Wb + (size_t)r * GK + cc * 8);
        }
        asm volatile("cp.async.commit_group;");
    };

    issue(0, 0);
    issue(1, 1);

    // ldmatrix per-lane offsets (bytes)
    const uint32_t a_lane_off =
        (uint32_t)((wm * 32 + (lane & 15)) * AP + ((lane >> 4) * 8)) * 2u;
    const uint32_t b_lane_off =
        (uint32_t)((wn * 64 + (lane & 7) + ((lane >> 4) & 1) * 8) * AP
                   + (((lane >> 3) & 1) * 8)) * 2u;

    uint32_t af[2][2][4], bf[2][4][4];

#define LDA(buf, ksi) do { \
        ldsm4(af[buf][0], aaddr + (uint32_t)((ksi) * 16) * 2u); \
        ldsm4(af[buf][1], aaddr + (uint32_t)(16 * AP + (ksi) * 16) * 2u); \
    } while (0)
#define LDB(buf, ksi) do { \
        ldsm4(bf[buf][0], baddr + (uint32_t)((ksi) * 16) * 2u); \
        ldsm4(bf[buf][1], baddr + (uint32_t)(16 * AP + (ksi) * 16) * 2u); \
        ldsm4(bf[buf][2], baddr + (uint32_t)(32 * AP + (ksi) * 16) * 2u); \
        ldsm4(bf[buf][3], baddr + (uint32_t)(48 * AP + (ksi) * 16) * 2u); \
    } while (0)

    for (int t = 0; t < NT; ++t) {
        if (t + 1 < NT) {
            asm volatile("cp.async.wait_group 1;");
        } else {
            asm volatile("cp.async.wait_group 0;");
        }
        __syncthreads();
        if (t + 2 < NT) issue(t + 2, (t + 2) % 3);

        const uint32_t sa = sbase + (uint32_t)(t % 3) * STGH * 2u;
        const uint32_t aaddr = sa + a_lane_off;
        const uint32_t baddr = sa + ASTGH * 2u + b_lane_off;

        LDA(0, 0);
        LDB(0, 0);
#pragma unroll
        for (int ks = 0; ks < 4; ++ks) {
            const int cur = ks & 1;
            if (ks < 3) {
                LDA(cur ^ 1, ks + 1);
                LDB(cur ^ 1, ks + 1);
            }
#pragma unroll
            for (int ms = 0; ms < 2; ms++)
#pragma unroll
                for (int np = 0; np < 4; np++) {
                    mma_f16(acc[ms][np * 2], af[cur][ms], bf[cur][np]);
                    mma_f16(acc[ms][np * 2 + 1], af[cur][ms], bf[cur][np] + 2);
                }
        }
    }
#undef LDA
#undef LDB

    float2 bv[8];
#pragma unroll
    for (int ns = 0; ns < 8; ns++) {
        const int col = n0 + wn * 64 + ns * 8 + 2 * (lane & 3);
        bv[ns] = *(const float2*)(bias + col);
    }

    if (half_out) {
        __half* C = (__half*)Cout;
#pragma unroll
        for (int ms = 0; ms < 2; ms++) {
            const int row0 = m0 + wm * 32 + ms * 16 + (lane >> 2);
#pragma unroll
            for (int ns = 0; ns < 8; ns++) {
                const int col = n0 + wn * 64 + ns * 8 + 2 * (lane & 3);
                __half2 v0 = __floats2half2_rn((acc[ms][ns][0] + bv[ns].x) * scale,
                                               (acc[ms][ns][1] + bv[ns].y) * scale);
                __half2 v1 = __floats2half2_rn((acc[ms][ns][2] + bv[ns].x) * scale,
                                               (acc[ms][ns][3] + bv[ns].y) * scale);
                *(__half2*)(C + (size_t)row0 * GN + col) = v0;
                *(__half2*)(C + (size_t)(row0 + 8) * GN + col) = v1;
            }
        }
    } else {
        float* C = (float*)Cout;
#pragma unroll
        for (int ms = 0; ms < 2; ms++) {
            const int row0 = m0 + wm * 32 + ms * 16 + (lane >> 2);
#pragma unroll
            for (int ns = 0; ns < 8; ns++) {
                const int col = n0 + wn * 64 + ns * 8 + 2 * (lane & 3);
                float2 v0 = make_float2(acc[ms][ns][0] + bv[ns].x,
                                        acc[ms][ns][1] + bv[ns].y);
                float2 v1 = make_float2(acc[ms][ns][2] + bv[ns].x,
                                        acc[ms][ns][3] + bv[ns].y);
                *(float2*)(C + (size_t)row0 * GN + col) = v0;
                *(float2*)(C + (size_t)(row0 + 8) * GN + col) = v1;
            }
        }
    }
}

// fused Q/K/V projection: blockIdx.z selects the stream
__global__ __launch_bounds__(512, 1)
void gemm_qkv(const __half* __restrict__ xq, const __half* __restrict__ xk,
              const __half* __restrict__ xv,
              const __half* __restrict__ wq, const __half* __restrict__ wk,
              const __half* __restrict__ wv,
              const float* __restrict__ bq, const float* __restrict__ bk,
              const float* __restrict__ bv,
              __half* __restrict__ pq, __half* __restrict__ pk,
              __half* __restrict__ pv)
{
    const int z = blockIdx.z;
    const __half* A = (z == 0) ? xq : (z == 1) ? xk : xv;
    const __half* W = (z == 0) ? wq : (z == 1) ? wk : wv;
    const float* bias = (z == 0) ? bq : (z == 1) ? bk : bv;
    __half* C = (z == 0) ? pq : (z == 1) ? pk : pv;
    const float scale = (z == 0) ? ATT_SCALE : 1.0f;
    gemm_core(A, W, bias, C, scale, 1, blockIdx.x, blockIdx.y);
}

__global__ __launch_bounds__(512, 1)
void gemm_one(const __half* __restrict__ A, const __half* __restrict__ W,
              const float* __restrict__ bias, void* __restrict__ Cout,
              float scale, int half_out)
{
    gemm_core(A, W, bias, Cout, scale, half_out, blockIdx.x, blockIdx.y);
}

// ===========================================================================
// fp16 flash attention v2 (unchanged from R6): register P, ldsm x4.
// ===========================================================================
#define FP 136
#define TILE_H (128 * FP)
#define FLASH_SMEM (TILE_H * 2 * 5)   // 174080 B

__global__ __launch_bounds__(256, 1)
void flash_tc(const __half* __restrict__ Q, const __half* __restrict__ K,
              const __half* __restrict__ V, __half* __restrict__ O)
{
    extern __shared__ __half fsmh[];

    const int qt = (SEQ / 128) - 1 - blockIdx.x;
    const int h = blockIdx.y;
    const int b = blockIdx.z;
    const int q0 = qt * 128;
    const size_t headoff = (size_t)b * SEQ * DMODEL + (size_t)h * HDIM;
    const __half* Qb = Q + headoff;
    const __half* Kb = K + headoff;
    const __half* Vb = V + headoff;

    const int tid = threadIdx.x;
    const int lane = tid & 31;
    const int warp = tid >> 5;
    const int g = lane >> 2;
    const int q4 = lane & 3;

    const uint32_t sQ = smem_u32(fsmh);
    const uint32_t sK0 = sQ + TILE_H * 2u;
    const uint32_t sV0 = sQ + 3u * TILE_H * 2u;

#pragma unroll
    for (int i = 0; i < 8; ++i) {
        const int slot = tid + i * 256;
        const int r = slot >> 4, c = slot & 15;
        cp16(sQ + (uint32_t)(r * FP + c * 8) * 2u,
             Qb + (size_t)(q0 + r) * DMODEL + c * 8);
    }

    auto issue_kv = [&](int kt) {
        const int buf = kt & 1;
        const int k0 = kt * 128;
        const uint32_t dK = sK0 + (uint32_t)buf * TILE_H * 2u;
        const uint32_t dV = sV0 + (uint32_t)buf * TILE_H * 2u;
#pragma unroll
        for (int i = 0; i < 8; ++i) {
            const int slot = tid + i * 256;
            const int r = slot >> 4, c = slot & 15;
            cp16(dK + (uint32_t)(r * FP + c * 8) * 2u,
                 Kb + (size_t)(k0 + r) * DMODEL + c * 8);
            cp16(dV + (uint32_t)(r * FP + c * 8) * 2u,
                 Vb + (size_t)(k0 + r) * DMODEL + c * 8);
        }
        asm volatile("cp.async.commit_group;");
    };

    issue_kv(0);
    if (qt > 0) issue_kv(1);

    float m0 = -INFINITY, m1 = -INFINITY, l0 = 0.0f, l1 = 0.0f;
    float acco[16][4];
#pragma unroll
    for (int j = 0; j < 16; j++)
#pragma unroll
        for (int r = 0; r < 4; r++) acco[j][r] = 0.0f;

    const int ar = warp * 16 + g;

    const uint32_t qa_off =
        (uint32_t)((warp * 16 + (lane & 15)) * FP + ((lane >> 4) * 8)) * 2u;
    const uint32_t kb4_off =
        (uint32_t)(((lane & 7) + ((lane >> 4) & 1) * 8) * FP
                   + (((lane >> 3) & 1) * 8)) * 2u;
    const uint32_t vt4_off =
        (uint32_t)(((lane & 7) + ((lane >> 3) & 1) * 8) * FP
                   + ((lane >> 4) * 8)) * 2u;

    uint32_t qf[8][4];
    bool qloaded = false;

    for (int kt = 0; kt <= qt; ++kt) {
        const int buf = kt & 1;
        const uint32_t sKc = sK0 + (uint32_t)buf * TILE_H * 2u;
        const uint32_t sVc = sV0 + (uint32_t)buf * TILE_H * 2u;

        if (kt < qt) {
            asm volatile("cp.async.wait_group 1;");
        } else {
            asm volatile("cp.async.wait_group 0;");
        }
        __syncthreads();

        if (!qloaded) {
#pragma unroll
            for (int ks = 0; ks < 8; ++ks)
                ldsm4(qf[ks], sQ + qa_off + (uint32_t)(ks * 16) * 2u);
            qloaded = true;
        }

        float accs[16][4];
#pragma unroll
        for (int j = 0; j < 16; j++)
#pragma unroll
            for (int r = 0; r < 4; r++) accs[j][r] = 0.0f;

#pragma unroll
        for (int ks = 0; ks < 8; ++ks) {
#pragma unroll
            for (int jp = 0; jp < 8; ++jp) {
                uint32_t bb[4];
                ldsm4(bb, sKc + kb4_off + (uint32_t)(jp * 16 * FP + ks * 16) * 2u);
                mma_f16(accs[jp * 2], qf[ks], bb);
                mma_f16(accs[jp * 2 + 1], qf[ks], bb + 2);
            }
        }

        if (kt == qt) {
#pragma unroll
            for (int j = 0; j < 16; ++j) {
                const int c0 = j * 8 + 2 * q4;
                if (c0 > ar)          accs[j][0] = -1e30f;
                if (c0 + 1 > ar)      accs[j][1] = -1e30f;
                if (c0 > ar + 8)      accs[j][2] = -1e30f;
                if (c0 + 1 > ar + 8)  accs[j][3] = -1e30f;
            }
        }

        float mx0 = -INFINITY, mx1 = -INFINITY;
#pragma unroll
        for (int j = 0; j < 16; ++j) {
            mx0 = fmaxf(mx0, fmaxf(accs[j][0], accs[j][1]));
            mx1 = fmaxf(mx1, fmaxf(accs[j][2], accs[j][3]));
        }
        mx0 = fmaxf(mx0, __shfl_xor_sync(0xffffffffu, mx0, 1));
        mx0 = fmaxf(mx0, __shfl_xor_sync(0xffffffffu, mx0, 2));
        mx1 = fmaxf(mx1, __shfl_xor_sync(0xffffffffu, mx1, 1));
        mx1 = fmaxf(mx1, __shfl_xor_sync(0xffffffffu, mx1, 2));
        const float mn0 = fmaxf(m0, mx0);
        const float mn1 = fmaxf(m1, mx1);
        const float cr0 = __expf(m0 - mn0);
        const float cr1 = __expf(m1 - mn1);
        float s0 = 0.0f, s1 = 0.0f;
#pragma unroll
        for (int j = 0; j < 16; ++j) {
            accs[j][0] = __expf(accs[j][0] - mn0); s0 += accs[j][0];
            accs[j][1] = __expf(accs[j][1] - mn0); s0 += accs[j][1];
            accs[j][2] = __expf(accs[j][2] - mn1); s1 += accs[j][2];
            accs[j][3] = __expf(accs[j][3] - mn1); s1 += accs[j][3];
        }
        s0 += __shfl_xor_sync(0xffffffffu, s0, 1);
        s0 += __shfl_xor_sync(0xffffffffu, s0, 2);
        s1 += __shfl_xor_sync(0xffffffffu, s1, 1);
        s1 += __shfl_xor_sync(0xffffffffu, s1, 2);
        l0 = l0 * cr0 + s0;  m0 = mn0;
        l1 = l1 * cr1 + s1;  m1 = mn1;
#pragma unroll
        for (int j = 0; j < 16; ++j) {
            acco[j][0] *= cr0; acco[j][1] *= cr0;
            acco[j][2] *= cr1; acco[j][3] *= cr1;
        }

#pragma unroll
        for (int t = 0; t < 8; ++t) {
            uint32_t a[4];
            a[0] = pack_h2(accs[2 * t][0], accs[2 * t][1]);
            a[1] = pack_h2(accs[2 * t][2], accs[2 * t][3]);
            a[2] = pack_h2(accs[2 * t + 1][0], accs[2 * t + 1][1]);
            a[3] = pack_h2(accs[2 * t + 1][2], accs[2 * t + 1][3]);
#pragma unroll
            for (int jp = 0; jp < 8; ++jp) {
                uint32_t bb[4];
                ldsm4t(bb, sVc + vt4_off + (uint32_t)(t * 16 * FP + jp * 16) * 2u);
                mma_f16(acco[jp * 2], a, bb);
                mma_f16(acco[jp * 2 + 1], a, bb + 2);
            }
        }

        __syncthreads();
        if (kt + 2 <= qt) issue_kv(kt + 2);
    }

    const float i0 = 1.0f / l0;
    const float i1 = 1.0f / l1;
#pragma unroll
    for (int j = 0; j < 16; ++j) {
        *(__half2*)(O + headoff + (size_t)(q0 + ar) * DMODEL + j * 8 + 2 * q4) =
            __floats2half2_rn(acco[j][0] * i0, acco[j][1] * i0);
        *(__half2*)(O + headoff + (size_t)(q0 + ar + 8) * DMODEL + j * 8 + 2 * q4) =
            __floats2half2_rn(acco[j][2] * i1, acco[j][3] * i1);
    }
}

// ---------------------------------------------------------------------------
extern "C" void kernel_launch(void* const* d_in, const int* in_sizes, int n_in,
                              void* d_out, int out_size)
{
    const float* query = (const float*)d_in[0];
    const float* key_i = (const float*)d_in[1];
    const float* value = (const float*)d_in[2];
    const float* Wq = (const float*)d_in[3];
    const float* bq = (const float*)d_in[4];
    const float* Wk = (const float*)d_in[5];
    const float* bk = (const float*)d_in[6];
    const float* Wv = (const float*)d_in[7];
    const float* bv = (const float*)d_in[8];
    const float* Wo = (const float*)d_in[9];
    const float* bo = (const float*)d_in[10];
    float* out = (float*)d_out;

    __half *xq, *xk, *xv, *wq, *wk, *wv, *wo, *pq, *pk, *pv, *pa;
    cudaGetSymbolAddress((void**)&xq, hx_q);
    cudaGetSymbolAddress((void**)&xk, hx_k);
    cudaGetSymbolAddress((void**)&xv, hx_v);
    cudaGetSymbolAddress((void**)&wq, hw_q);
    cudaGetSymbolAddress((void**)&wk, hw_k);
    cudaGetSymbolAddress((void**)&wv, hw_v);
    cudaGetSymbolAddress((void**)&wo, hw_o);
    cudaGetSymbolAddress((void**)&pq, h_q);
    cudaGetSymbolAddress((void**)&pk, h_k);
    cudaGetSymbolAddress((void**)&pv, h_v);
    cudaGetSymbolAddress((void**)&pa, h_a);

    const int act4 = (MROWS * DMODEL) / 4;
    const int w4 = (DMODEL * DMODEL) / 4;
    conv_act<<<dim3((act4 + 255) / 256, 3), 256>>>(
        (const float4*)query, (const float4*)key_i, (const float4*)value,
        (uint2*)xq, (uint2*)xk, (uint2*)xv, act4);
    conv_w<<<dim3((w4 + 255) / 256, 4), 256>>>(
        (const float4*)Wq, (const float4*)Wk, (const float4*)Wv,
        (const float4*)Wo, (uint2*)wq, (uint2*)wk, (uint2*)wv, (uint2*)wo, w4);

    cudaFuncSetAttribute(gemm_qkv, cudaFuncAttributeMaxDynamicSharedMemorySize,
                         GEMM_SMEM);
    cudaFuncSetAttribute(gemm_one, cudaFuncAttributeMaxDynamicSharedMemorySize,
                         GEMM_SMEM);

    gemm_qkv<<<dim3(GN / TBN, MROWS / TBM, 3), 512, GEMM_SMEM>>>(
        xq, xk, xv, wq, wk, wv, bq, bk, bv, pq, pk, pv);

    cudaFuncSetAttribute(flash_tc, cudaFuncAttributeMaxDynamicSharedMemorySize,
                         FLASH_SMEM);
    const dim3 agrid(SEQ / 128, NHEAD, BATCH);
    flash_tc<<<agrid, 256, FLASH_SMEM>>>(pq, pk, pv, pa);

    gemm_one<<<dim3(GN / TBN, MROWS / TBM), 512, GEMM_SMEM>>>(
        pa, wo, bo, out, 1.0f, 0);
}